// round 2
// baseline (speedup 1.0000x reference)
#include <cuda_runtime.h>

#define NN 50000
#define EE 800000
#define ET (EE + NN)
#define CH 64

// ---------------- scratch (static device globals; no allocation) ----------------
__device__ float g_h[(size_t)NN * CH];   // h = X @ W for current layer
__device__ float g_o[(size_t)NN * CH];   // aggregated output (input to next layer)
__device__ float g_as[NN];               // alpha_src per node
__device__ float g_ad[NN];               // alpha_dst per node
__device__ int   g_deg[NN];
__device__ int   g_cur[NN];
__device__ int   g_off[NN + 1];
__device__ int   g_ssrc[ET];             // CSR-by-dst: source node of each edge

// ---------------- CSR construction ----------------
__global__ void zero_kernel(int n) {
    int stride = gridDim.x * blockDim.x;
    for (int i = blockIdx.x * blockDim.x + threadIdx.x; i < n; i += stride) {
        g_deg[i] = 0;
        g_cur[i] = 0;
    }
}

__global__ void count_kernel(const int* __restrict__ ei, int E, int n) {
    int tot = E + n;
    int stride = gridDim.x * blockDim.x;
    for (int e = blockIdx.x * blockDim.x + threadIdx.x; e < tot; e += stride) {
        int dst = (e < E) ? ei[E + e] : (e - E);
        atomicAdd(&g_deg[dst], 1);
    }
}

// single-block exclusive scan of g_deg -> g_off (n up to 50000)
__global__ void scan_kernel(int n) {
    __shared__ int warp_sums[32];
    __shared__ int s_carry;
    if (threadIdx.x == 0) s_carry = 0;
    __syncthreads();
    int lane = threadIdx.x & 31, wid = threadIdx.x >> 5;
    for (int base = 0; base < n; base += 1024) {
        int i = base + (int)threadIdx.x;
        int v = (i < n) ? g_deg[i] : 0;
        int incl = v;
        #pragma unroll
        for (int off = 1; off < 32; off <<= 1) {
            int t = __shfl_up_sync(0xffffffffu, incl, off);
            if (lane >= off) incl += t;
        }
        if (lane == 31) warp_sums[wid] = incl;
        __syncthreads();
        if (wid == 0) {
            int ws = warp_sums[lane];
            #pragma unroll
            for (int off = 1; off < 32; off <<= 1) {
                int t = __shfl_up_sync(0xffffffffu, ws, off);
                if (lane >= off) ws += t;
            }
            warp_sums[lane] = ws;   // inclusive warp-sum scan
        }
        __syncthreads();
        int warp_off = (wid == 0) ? 0 : warp_sums[wid - 1];
        int excl = s_carry + warp_off + incl - v;
        if (i < n) g_off[i] = excl;
        __syncthreads();
        if (threadIdx.x == 1023) s_carry += warp_sums[31];
        __syncthreads();
    }
    if (threadIdx.x == 0) g_off[n] = s_carry;
}

__global__ void fill_kernel(const int* __restrict__ ei, int E, int n) {
    int tot = E + n;
    int stride = gridDim.x * blockDim.x;
    for (int e = blockIdx.x * blockDim.x + threadIdx.x; e < tot; e += stride) {
        int src, dst;
        if (e < E) { src = ei[e]; dst = ei[E + e]; }
        else       { src = e - E; dst = src; }
        int p = atomicAdd(&g_cur[dst], 1);
        g_ssrc[g_off[dst] + p] = src;
    }
}

// ---------------- GEMM + fused alpha dot products ----------------
// One warp per row. lane holds channels {lane, lane+32}. W staged in smem.
template <int CIN>
__global__ void gemm_alpha_kernel(const float* __restrict__ Xin,
                                  const float* __restrict__ W,
                                  const float* __restrict__ avs,
                                  const float* __restrict__ avd,
                                  int n) {
    __shared__ float sW[CIN * CH];
    const float* X = Xin ? Xin : g_o;   // layers 2/3 read previous layer output
    for (int i = threadIdx.x; i < CIN * CH; i += blockDim.x) sW[i] = W[i];
    __syncthreads();

    int lane = threadIdx.x & 31;
    int warp = threadIdx.x >> 5;
    int gw = blockIdx.x * (blockDim.x >> 5) + warp;
    int nw = gridDim.x * (blockDim.x >> 5);

    float a0 = avs[lane], a1 = avs[lane + 32];
    float d0 = avd[lane], d1 = avd[lane + 32];

    for (int row = gw; row < n; row += nw) {
        const float* xr = X + (size_t)row * CIN;
        float xv[CIN / 32];
        #pragma unroll
        for (int g = 0; g < CIN / 32; g++) xv[g] = xr[g * 32 + lane];

        float acc0 = 0.f, acc1 = 0.f;
        #pragma unroll
        for (int k = 0; k < CIN; k++) {
            float xk = __shfl_sync(0xffffffffu, xv[k >> 5], k & 31);
            acc0 = fmaf(xk, sW[k * CH + lane], acc0);
            acc1 = fmaf(xk, sW[k * CH + lane + 32], acc1);
        }
        g_h[(size_t)row * CH + lane] = acc0;
        g_h[(size_t)row * CH + lane + 32] = acc1;

        float ps = acc0 * a0 + acc1 * a1;
        float pd = acc0 * d0 + acc1 * d1;
        #pragma unroll
        for (int o = 16; o; o >>= 1) {
            ps += __shfl_xor_sync(0xffffffffu, ps, o);
            pd += __shfl_xor_sync(0xffffffffu, pd, o);
        }
        if (lane == 0) { g_as[row] = ps; g_ad[row] = pd; }
    }
}

// ---------------- segment softmax + weighted aggregation ----------------
// One warp per destination node. mode==0: write g_o with ELU; mode==1: write dout raw.
__global__ void agg_kernel(const float* __restrict__ bias,
                           float* __restrict__ dout, int n, int mode) {
    int lane = threadIdx.x & 31;
    int gw = (blockIdx.x * blockDim.x + threadIdx.x) >> 5;
    int nw = (gridDim.x * blockDim.x) >> 5;
    float* out = mode ? dout : g_o;

    for (int d = gw; d < n; d += nw) {
        int beg = g_off[d], end = g_off[d + 1];
        float adv = g_ad[d];

        // pass 1: segment max (lane-parallel over edges)
        float m = -1e30f;
        for (int j = beg + lane; j < end; j += 32) {
            float e = g_as[g_ssrc[j]] + adv;
            e = e > 0.f ? e : 0.2f * e;
            m = fmaxf(m, e);
        }
        #pragma unroll
        for (int o = 16; o; o >>= 1) m = fmaxf(m, __shfl_xor_sync(0xffffffffu, m, o));

        // pass 2: weighted accumulate (serial over edges, lanes = channels), x2 unroll
        float acc0 = 0.f, acc1 = 0.f, acc2 = 0.f, acc3 = 0.f, den = 0.f;
        int j = beg;
        for (; j + 1 < end; j += 2) {
            int s0 = g_ssrc[j], s1 = g_ssrc[j + 1];
            float e0 = g_as[s0] + adv; e0 = e0 > 0.f ? e0 : 0.2f * e0;
            float e1 = g_as[s1] + adv; e1 = e1 > 0.f ? e1 : 0.2f * e1;
            float w0 = __expf(e0 - m);
            float w1 = __expf(e1 - m);
            den += w0 + w1;
            const float* h0 = g_h + (size_t)s0 * CH;
            const float* h1 = g_h + (size_t)s1 * CH;
            acc0 += w0 * h0[lane];
            acc1 += w0 * h0[lane + 32];
            acc2 += w1 * h1[lane];
            acc3 += w1 * h1[lane + 32];
        }
        if (j < end) {
            int s0 = g_ssrc[j];
            float e0 = g_as[s0] + adv; e0 = e0 > 0.f ? e0 : 0.2f * e0;
            float w0 = __expf(e0 - m);
            den += w0;
            const float* h0 = g_h + (size_t)s0 * CH;
            acc0 += w0 * h0[lane];
            acc1 += w0 * h0[lane + 32];
        }
        acc0 += acc2;
        acc1 += acc3;

        float inv = 1.f / den;
        float o0 = acc0 * inv + bias[lane];
        float o1 = acc1 * inv + bias[lane + 32];
        if (mode == 0) {  // ELU for layers 1 & 2
            o0 = o0 > 0.f ? o0 : (__expf(o0) - 1.f);
            o1 = o1 > 0.f ? o1 : (__expf(o1) - 1.f);
        }
        out[(size_t)d * CH + lane] = o0;
        out[(size_t)d * CH + lane + 32] = o1;
    }
}

// ---------------- launch ----------------
extern "C" void kernel_launch(void* const* d_in, const int* in_sizes, int n_in,
                              void* d_out, int out_size) {
    const float* x     = (const float*)d_in[0];
    const int*   ei    = (const int*)d_in[1];
    const float* W1    = (const float*)d_in[2];
    const float* asr1  = (const float*)d_in[3];
    const float* adt1  = (const float*)d_in[4];
    const float* b1    = (const float*)d_in[5];
    const float* W2    = (const float*)d_in[6];
    const float* asr2  = (const float*)d_in[7];
    const float* adt2  = (const float*)d_in[8];
    const float* b2    = (const float*)d_in[9];
    const float* W3    = (const float*)d_in[10];
    const float* asr3  = (const float*)d_in[11];
    const float* adt3  = (const float*)d_in[12];
    const float* b3    = (const float*)d_in[13];

    int n = in_sizes[0] / 128;   // 50000
    int E = in_sizes[1] / 2;     // 800000
    float* dout = (float*)d_out;

    // CSR build (same every call; recomputed for determinism within the graph)
    zero_kernel<<<256, 256>>>(n);
    count_kernel<<<832, 256>>>(ei, E, n);
    scan_kernel<<<1, 1024>>>(n);
    fill_kernel<<<832, 256>>>(ei, E, n);

    int aggGrid = (n * 32 + 255) / 256;

    // layer 1: x[N,128] -> h1; agg + ELU -> g_o
    gemm_alpha_kernel<128><<<1024, 256>>>(x, W1, asr1, adt1, n);
    agg_kernel<<<aggGrid, 256>>>(b1, dout, n, 0);

    // layer 2: g_o -> h2; agg + ELU -> g_o
    gemm_alpha_kernel<64><<<1024, 256>>>(nullptr, W2, asr2, adt2, n);
    agg_kernel<<<aggGrid, 256>>>(b2, dout, n, 0);

    // layer 3: g_o -> h3; agg (no ELU) -> d_out
    gemm_alpha_kernel<64><<<1024, 256>>>(nullptr, W3, asr3, adt3, n);
    agg_kernel<<<aggGrid, 256>>>(b3, dout, n, 1);
}

// round 3
// speedup vs baseline: 1.8254x; 1.8254x over previous
#include <cuda_runtime.h>

#define NN 50000
#define EE 800000
#define ET (EE + NN)
#define CH 64

// ---------------- scratch (static device globals; no allocation) ----------------
__device__ float g_h[(size_t)NN * CH];   // h = X @ W for current layer (float2/lane layout)
__device__ float g_o[(size_t)NN * CH];   // aggregated output (input to next layer)
__device__ float g_as[NN];               // alpha_src per node
__device__ float g_ad[NN];               // alpha_dst per node
__device__ int   g_deg[NN];
__device__ int   g_cur[NN];
__device__ int   g_off[NN + 1];
__device__ int   g_bsum[256];
__device__ int   g_ssrc[ET];             // CSR-by-dst: source node of each edge

// ---------------- CSR construction ----------------
__global__ void zero_kernel(int n) {
    int stride = gridDim.x * blockDim.x;
    for (int i = blockIdx.x * blockDim.x + threadIdx.x; i < n; i += stride) {
        g_deg[i] = 0;
        g_cur[i] = 0;
    }
}

__global__ void count_kernel(const int* __restrict__ ei, int E, int n) {
    int tot = E + n;
    int stride = gridDim.x * blockDim.x;
    for (int e = blockIdx.x * blockDim.x + threadIdx.x; e < tot; e += stride) {
        int dst = (e < E) ? ei[E + e] : (e - E);
        atomicAdd(&g_deg[dst], 1);
    }
}

// hierarchical exclusive scan of g_deg -> g_off
__global__ void scan1_kernel(int n) {
    __shared__ int wsum[8];
    __shared__ int wpre[8];
    int i = blockIdx.x * blockDim.x + threadIdx.x;
    int lane = threadIdx.x & 31, wid = threadIdx.x >> 5;
    int v = (i < n) ? g_deg[i] : 0;
    int incl = v;
    #pragma unroll
    for (int off = 1; off < 32; off <<= 1) {
        int t = __shfl_up_sync(0xffffffffu, incl, off);
        if (lane >= off) incl += t;
    }
    if (lane == 31) wsum[wid] = incl;
    __syncthreads();
    if (threadIdx.x == 0) {
        int run = 0;
        #pragma unroll
        for (int w = 0; w < 8; w++) { wpre[w] = run; run += wsum[w]; }
        g_bsum[blockIdx.x] = run;
    }
    __syncthreads();
    if (i < n) g_off[i] = wpre[wid] + incl - v;
}

__global__ void scan2_kernel(int nb, int n) {   // <<<1,32>>>
    int lane = threadIdx.x;
    int carry = 0;
    for (int base = 0; base < nb; base += 32) {
        int i = base + lane;
        int v = (i < nb) ? g_bsum[i] : 0;
        int incl = v;
        #pragma unroll
        for (int off = 1; off < 32; off <<= 1) {
            int t = __shfl_up_sync(0xffffffffu, incl, off);
            if (lane >= off) incl += t;
        }
        if (i < nb) g_bsum[i] = carry + incl - v;
        carry += __shfl_sync(0xffffffffu, incl, 31);
    }
    if (lane == 0) g_off[n] = carry;
}

__global__ void scan3_kernel(int n) {
    int i = blockIdx.x * blockDim.x + threadIdx.x;
    if (i < n) g_off[i] += g_bsum[i >> 8];
}

__global__ void fill_kernel(const int* __restrict__ ei, int E, int n) {
    int tot = E + n;
    int stride = gridDim.x * blockDim.x;
    for (int e = blockIdx.x * blockDim.x + threadIdx.x; e < tot; e += stride) {
        int src, dst;
        if (e < E) { src = ei[e]; dst = ei[E + e]; }
        else       { src = e - E; dst = src; }
        int p = atomicAdd(&g_cur[dst], 1);
        g_ssrc[g_off[dst] + p] = src;
    }
}

// ---------------- GEMM + fused alpha dot products ----------------
// One warp per row. lane holds channels {2*lane, 2*lane+1}. W staged in smem.
template <int CIN>
__global__ void gemm_alpha_kernel(const float* __restrict__ Xin,
                                  const float* __restrict__ W,
                                  const float* __restrict__ avs,
                                  const float* __restrict__ avd,
                                  int n) {
    __shared__ float sW[CIN * CH];
    const float* X = Xin ? Xin : g_o;   // layers 2/3 read previous layer output
    for (int i = threadIdx.x; i < CIN * CH; i += blockDim.x) sW[i] = W[i];
    __syncthreads();
    const float2* sW2 = (const float2*)sW;

    int lane = threadIdx.x & 31;
    int warp = threadIdx.x >> 5;
    int gw = blockIdx.x * (blockDim.x >> 5) + warp;
    int nw = gridDim.x * (blockDim.x >> 5);

    float a0 = avs[2 * lane], a1 = avs[2 * lane + 1];
    float d0 = avd[2 * lane], d1 = avd[2 * lane + 1];
    float2* h2 = (float2*)g_h;

    for (int row = gw; row < n; row += nw) {
        const float* xr = X + (size_t)row * CIN;
        float xv[CIN / 32];
        #pragma unroll
        for (int g = 0; g < CIN / 32; g++) xv[g] = xr[g * 32 + lane];

        float acc0 = 0.f, acc1 = 0.f;
        #pragma unroll
        for (int k = 0; k < CIN; k++) {
            float xk = __shfl_sync(0xffffffffu, xv[k >> 5], k & 31);
            float2 wv = sW2[k * 32 + lane];
            acc0 = fmaf(xk, wv.x, acc0);
            acc1 = fmaf(xk, wv.y, acc1);
        }
        float2 hv; hv.x = acc0; hv.y = acc1;
        h2[(size_t)row * 32 + lane] = hv;

        float ps = acc0 * a0 + acc1 * a1;
        float pd = acc0 * d0 + acc1 * d1;
        #pragma unroll
        for (int o = 16; o; o >>= 1) {
            ps += __shfl_xor_sync(0xffffffffu, ps, o);
            pd += __shfl_xor_sync(0xffffffffu, pd, o);
        }
        if (lane == 0) { g_as[row] = ps; g_ad[row] = pd; }
    }
}

// ---------------- segment softmax + weighted aggregation ----------------
// One warp per destination node. No max-shift (exp args are O(10), safe in fp32).
// Phase A (lane-parallel): gather alpha_src, compute edge weights into registers.
// Phase B (channel-parallel): shfl-broadcast (s,w), gather h rows as float2.
__global__ void agg_kernel(const float* __restrict__ bias,
                           float* __restrict__ dout, int n, int mode) {
    int lane = threadIdx.x & 31;
    int gw = (blockIdx.x * blockDim.x + threadIdx.x) >> 5;
    int nw = (gridDim.x * blockDim.x) >> 5;
    float* out = mode ? dout : g_o;
    const float2* h2 = (const float2*)g_h;

    for (int d = gw; d < n; d += nw) {
        int beg = g_off[d], end = g_off[d + 1];
        float adv = g_ad[d];

        float acc0 = 0.f, acc1 = 0.f, denp = 0.f;
        for (int base = beg; base < end; base += 32) {
            int j = base + lane;
            int s = 0;
            float w = 0.f;
            if (j < end) {
                s = g_ssrc[j];
                float e = g_as[s] + adv;
                e = e > 0.f ? e : 0.2f * e;
                w = __expf(e);
            }
            denp += w;
            int cnt = min(32, end - base);
            #pragma unroll 4
            for (int k = 0; k < cnt; k++) {
                int   sk = __shfl_sync(0xffffffffu, s, k);
                float wk = __shfl_sync(0xffffffffu, w, k);
                float2 hv = h2[(size_t)sk * 32 + lane];
                acc0 = fmaf(wk, hv.x, acc0);
                acc1 = fmaf(wk, hv.y, acc1);
            }
        }
        float den = denp;
        #pragma unroll
        for (int o = 16; o; o >>= 1) den += __shfl_xor_sync(0xffffffffu, den, o);

        float inv = 1.f / den;
        float2 bv = ((const float2*)bias)[lane];
        float o0 = acc0 * inv + bv.x;
        float o1 = acc1 * inv + bv.y;
        if (mode == 0) {  // ELU for layers 1 & 2
            o0 = o0 > 0.f ? o0 : (__expf(o0) - 1.f);
            o1 = o1 > 0.f ? o1 : (__expf(o1) - 1.f);
        }
        float2 ov; ov.x = o0; ov.y = o1;
        ((float2*)out)[(size_t)d * 32 + lane] = ov;
    }
}

// ---------------- launch ----------------
extern "C" void kernel_launch(void* const* d_in, const int* in_sizes, int n_in,
                              void* d_out, int out_size) {
    const float* x     = (const float*)d_in[0];
    const int*   ei    = (const int*)d_in[1];
    const float* W1    = (const float*)d_in[2];
    const float* asr1  = (const float*)d_in[3];
    const float* adt1  = (const float*)d_in[4];
    const float* b1    = (const float*)d_in[5];
    const float* W2    = (const float*)d_in[6];
    const float* asr2  = (const float*)d_in[7];
    const float* adt2  = (const float*)d_in[8];
    const float* b2    = (const float*)d_in[9];
    const float* W3    = (const float*)d_in[10];
    const float* asr3  = (const float*)d_in[11];
    const float* adt3  = (const float*)d_in[12];
    const float* b3    = (const float*)d_in[13];

    int n = in_sizes[0] / 128;   // 50000
    int E = in_sizes[1] / 2;     // 800000
    float* dout = (float*)d_out;

    int nb = (n + 255) / 256;    // 196 scan blocks

    // CSR build
    zero_kernel<<<256, 256>>>(n);
    count_kernel<<<832, 256>>>(ei, E, n);
    scan1_kernel<<<nb, 256>>>(n);
    scan2_kernel<<<1, 32>>>(nb, n);
    scan3_kernel<<<nb, 256>>>(n);
    fill_kernel<<<832, 256>>>(ei, E, n);

    int aggGrid = (n * 32 + 255) / 256;

    // layer 1: x[N,128] -> h1; agg + ELU -> g_o
    gemm_alpha_kernel<128><<<1024, 256>>>(x, W1, asr1, adt1, n);
    agg_kernel<<<aggGrid, 256>>>(b1, dout, n, 0);

    // layer 2: g_o -> h2; agg + ELU -> g_o
    gemm_alpha_kernel<64><<<1024, 256>>>(nullptr, W2, asr2, adt2, n);
    agg_kernel<<<aggGrid, 256>>>(b2, dout, n, 0);

    // layer 3: g_o -> h3; agg (no ELU) -> d_out
    gemm_alpha_kernel<64><<<1024, 256>>>(nullptr, W3, asr3, adt3, n);
    agg_kernel<<<aggGrid, 256>>>(b3, dout, n, 1);
}

// round 4
// speedup vs baseline: 2.6856x; 1.4712x over previous
#include <cuda_runtime.h>

#define NN 50000
#define EE 800000
#define ET (EE + NN)
#define CH 64

typedef unsigned long long ull;

// ---------------- scratch (static device globals; no allocation) ----------------
__device__ float g_h[(size_t)NN * CH];   // h = X @ W (row-major [N][64])
__device__ float g_o[(size_t)NN * CH];   // aggregated output (input to next layer)
__device__ float g_as[NN];               // alpha_src per node
__device__ float g_ad[NN];               // alpha_dst per node
__device__ int   g_deg[NN];
__device__ int   g_cur[NN];              // fill cursor (= g_off copy)
__device__ int   g_off[NN + 1];
__device__ int   g_bsum[256];
__device__ int   g_ssrc[ET];             // CSR-by-dst: source node of each edge

// ---------------- f32x2 packed math helpers ----------------
__device__ __forceinline__ ull pack2(float x, float y) {
    ull r; asm("mov.b64 %0, {%1,%2};" : "=l"(r) : "f"(x), "f"(y)); return r;
}
__device__ __forceinline__ ull fma2(ull a, ull b, ull c) {
    ull d; asm("fma.rn.f32x2 %0, %1, %2, %3;" : "=l"(d) : "l"(a), "l"(b), "l"(c)); return d;
}
__device__ __forceinline__ void unpack2(ull p, float& x, float& y) {
    asm("mov.b64 {%0,%1}, %2;" : "=f"(x), "=f"(y) : "l"(p));
}

// ---------------- CSR construction ----------------
__global__ void zero_kernel(int n) {
    int stride = gridDim.x * blockDim.x;
    for (int i = blockIdx.x * blockDim.x + threadIdx.x; i < n; i += stride)
        g_deg[i] = 0;
}

__global__ void count_kernel(const int* __restrict__ ei, int E, int n) {
    int tot = E + n;
    int stride = gridDim.x * blockDim.x;
    for (int e = blockIdx.x * blockDim.x + threadIdx.x; e < tot; e += stride) {
        int dst = (e < E) ? ei[E + e] : (e - E);
        atomicAdd(&g_deg[dst], 1);
    }
}

// per-block exclusive scan of g_deg -> g_off (within-block), block sums -> g_bsum
__global__ void scan1_kernel(int n) {
    __shared__ int wsum[8];
    __shared__ int wpre[8];
    int i = blockIdx.x * blockDim.x + threadIdx.x;
    int lane = threadIdx.x & 31, wid = threadIdx.x >> 5;
    int v = (i < n) ? g_deg[i] : 0;
    int incl = v;
    #pragma unroll
    for (int off = 1; off < 32; off <<= 1) {
        int t = __shfl_up_sync(0xffffffffu, incl, off);
        if (lane >= off) incl += t;
    }
    if (lane == 31) wsum[wid] = incl;
    __syncthreads();
    if (threadIdx.x == 0) {
        int run = 0;
        #pragma unroll
        for (int w = 0; w < 8; w++) { wpre[w] = run; run += wsum[w]; }
        g_bsum[blockIdx.x] = run;
    }
    __syncthreads();
    if (i < n) g_off[i] = wpre[wid] + incl - v;
}

// fused: each block computes its own block-sum prefix (nb<=256 ints, trivial),
// adds it, and also initializes g_cur = g_off for the fill cursors.
__global__ void scan23_kernel(int nb, int n) {
    __shared__ int spre;
    if (threadIdx.x < 32) {
        int lane = threadIdx.x;
        int pre = 0, tot = 0;
        for (int i = lane; i < nb; i += 32) {
            int v = g_bsum[i];
            tot += v;
            if (i < (int)blockIdx.x) pre += v;
        }
        #pragma unroll
        for (int o = 16; o; o >>= 1) {
            pre += __shfl_xor_sync(0xffffffffu, pre, o);
            tot += __shfl_xor_sync(0xffffffffu, tot, o);
        }
        if (lane == 0) {
            spre = pre;
            if (blockIdx.x == 0) g_off[n] = tot;
        }
    }
    __syncthreads();
    int i = blockIdx.x * blockDim.x + threadIdx.x;
    if (i < n) {
        int v = g_off[i] + spre;
        g_off[i] = v;
        g_cur[i] = v;
    }
}

__global__ void fill_kernel(const int* __restrict__ ei, int E, int n) {
    int tot = E + n;
    int stride = gridDim.x * blockDim.x;
    for (int e = blockIdx.x * blockDim.x + threadIdx.x; e < tot; e += stride) {
        int src, dst;
        if (e < E) { src = ei[e]; dst = ei[E + e]; }
        else       { src = e - E; dst = src; }
        int p = atomicAdd(&g_cur[dst], 1);
        g_ssrc[p] = src;
    }
}

// ---------------- tiled GEMM (64x64 per block, f32x2 FMA) + fused alpha ----------------
// 256 threads: tx = tid&15 -> 4 cols (4*tx..), ty = tid>>4 -> 4 rows (4*ty..).
template <int CIN>
__global__ __launch_bounds__(256) void gemm_alpha_kernel(
        const float* __restrict__ Xin, const float* __restrict__ W,
        const float* __restrict__ avs, const float* __restrict__ avd, int n) {
    __shared__ float Xs[64][33];
    __shared__ float Ws[32][64];
    const float* X = Xin ? Xin : g_o;

    int tid = threadIdx.x;
    int tx = tid & 15, ty = tid >> 4;
    int m0 = blockIdx.x * 64;

    ull acc[4][2];
    #pragma unroll
    for (int r = 0; r < 4; r++) { acc[r][0] = pack2(0.f, 0.f); acc[r][1] = pack2(0.f, 0.f); }

    for (int k0 = 0; k0 < CIN; k0 += 32) {
        // stage X tile [64][32]
        {
            int r = tid >> 2, kq = (tid & 3) * 8;
            int row = min(m0 + r, n - 1);
            const float4* xp = (const float4*)(X + (size_t)row * CIN + k0 + kq);
            float4 v0 = xp[0], v1 = xp[1];
            Xs[r][kq + 0] = v0.x; Xs[r][kq + 1] = v0.y; Xs[r][kq + 2] = v0.z; Xs[r][kq + 3] = v0.w;
            Xs[r][kq + 4] = v1.x; Xs[r][kq + 5] = v1.y; Xs[r][kq + 6] = v1.z; Xs[r][kq + 7] = v1.w;
        }
        // stage W tile [32][64]
        {
            int kk = tid >> 3, c = (tid & 7) * 8;
            const float4* wp = (const float4*)(W + (size_t)(k0 + kk) * CH + c);
            *(float4*)&Ws[kk][c]     = wp[0];
            *(float4*)&Ws[kk][c + 4] = wp[1];
        }
        __syncthreads();

        #pragma unroll
        for (int kk = 0; kk < 32; kk++) {
            float4 wv = *(const float4*)&Ws[kk][tx * 4];
            ull wp0 = pack2(wv.x, wv.y);
            ull wp1 = pack2(wv.z, wv.w);
            #pragma unroll
            for (int r = 0; r < 4; r++) {
                float xv = Xs[ty * 4 + r][kk];
                ull xp = pack2(xv, xv);
                acc[r][0] = fma2(xp, wp0, acc[r][0]);
                acc[r][1] = fma2(xp, wp1, acc[r][1]);
            }
        }
        __syncthreads();
    }

    float c4[4][4];
    #pragma unroll
    for (int r = 0; r < 4; r++) {
        unpack2(acc[r][0], c4[r][0], c4[r][1]);
        unpack2(acc[r][1], c4[r][2], c4[r][3]);
    }

    float4 av = *(const float4*)&avs[tx * 4];
    float4 dv = *(const float4*)&avd[tx * 4];

    #pragma unroll
    for (int r = 0; r < 4; r++) {
        int row = m0 + ty * 4 + r;
        float ps = c4[r][0] * av.x + c4[r][1] * av.y + c4[r][2] * av.z + c4[r][3] * av.w;
        float pd = c4[r][0] * dv.x + c4[r][1] * dv.y + c4[r][2] * dv.z + c4[r][3] * dv.w;
        #pragma unroll
        for (int o = 8; o; o >>= 1) {
            ps += __shfl_xor_sync(0xffffffffu, ps, o, 16);
            pd += __shfl_xor_sync(0xffffffffu, pd, o, 16);
        }
        if (row < n) {
            float4 hv; hv.x = c4[r][0]; hv.y = c4[r][1]; hv.z = c4[r][2]; hv.w = c4[r][3];
            *(float4*)&g_h[(size_t)row * CH + tx * 4] = hv;
            if (tx == 0) { g_as[row] = ps; g_ad[row] = pd; }
        }
    }
}

// ---------------- segment softmax + weighted aggregation ----------------
// One warp per destination node. No max-shift (exp args are O(10), safe in fp32).
__global__ void agg_kernel(const float* __restrict__ bias,
                           float* __restrict__ dout, int n, int mode) {
    int lane = threadIdx.x & 31;
    int gw = (blockIdx.x * blockDim.x + threadIdx.x) >> 5;
    int nw = (gridDim.x * blockDim.x) >> 5;
    float* out = mode ? dout : g_o;
    const float2* h2 = (const float2*)g_h;

    for (int d = gw; d < n; d += nw) {
        int beg = g_off[d], end = g_off[d + 1];
        float adv = g_ad[d];

        float acc0 = 0.f, acc1 = 0.f, denp = 0.f;
        for (int base = beg; base < end; base += 32) {
            int j = base + lane;
            int s = 0;
            float w = 0.f;
            if (j < end) {
                s = g_ssrc[j];
                float e = g_as[s] + adv;
                e = e > 0.f ? e : 0.2f * e;
                w = __expf(e);
            }
            denp += w;
            int cnt = min(32, end - base);
            #pragma unroll 4
            for (int k = 0; k < cnt; k++) {
                int   sk = __shfl_sync(0xffffffffu, s, k);
                float wk = __shfl_sync(0xffffffffu, w, k);
                float2 hv = h2[(size_t)sk * 32 + lane];
                acc0 = fmaf(wk, hv.x, acc0);
                acc1 = fmaf(wk, hv.y, acc1);
            }
        }
        float den = denp;
        #pragma unroll
        for (int o = 16; o; o >>= 1) den += __shfl_xor_sync(0xffffffffu, den, o);

        float inv = 1.f / den;
        float2 bv = ((const float2*)bias)[lane];
        float o0 = acc0 * inv + bv.x;
        float o1 = acc1 * inv + bv.y;
        if (mode == 0) {  // ELU for layers 1 & 2
            o0 = o0 > 0.f ? o0 : (__expf(o0) - 1.f);
            o1 = o1 > 0.f ? o1 : (__expf(o1) - 1.f);
        }
        float2 ov; ov.x = o0; ov.y = o1;
        ((float2*)out)[(size_t)d * 32 + lane] = ov;
    }
}

// ---------------- launch ----------------
extern "C" void kernel_launch(void* const* d_in, const int* in_sizes, int n_in,
                              void* d_out, int out_size) {
    const float* x     = (const float*)d_in[0];
    const int*   ei    = (const int*)d_in[1];
    const float* W1    = (const float*)d_in[2];
    const float* asr1  = (const float*)d_in[3];
    const float* adt1  = (const float*)d_in[4];
    const float* b1    = (const float*)d_in[5];
    const float* W2    = (const float*)d_in[6];
    const float* asr2  = (const float*)d_in[7];
    const float* adt2  = (const float*)d_in[8];
    const float* b2    = (const float*)d_in[9];
    const float* W3    = (const float*)d_in[10];
    const float* asr3  = (const float*)d_in[11];
    const float* adt3  = (const float*)d_in[12];
    const float* b3    = (const float*)d_in[13];

    int n = in_sizes[0] / 128;   // 50000
    int E = in_sizes[1] / 2;     // 800000
    float* dout = (float*)d_out;

    int nb = (n + 255) / 256;    // 196 scan blocks

    // CSR build
    zero_kernel<<<256, 256>>>(n);
    count_kernel<<<832, 256>>>(ei, E, n);
    scan1_kernel<<<nb, 256>>>(n);
    scan23_kernel<<<nb, 256>>>(nb, n);
    fill_kernel<<<832, 256>>>(ei, E, n);

    int aggGrid = (n * 32 + 255) / 256;
    int gemmGrid = (n + 63) / 64;

    // layer 1: x[N,128] -> h1; agg + ELU -> g_o
    gemm_alpha_kernel<128><<<gemmGrid, 256>>>(x, W1, asr1, adt1, n);
    agg_kernel<<<aggGrid, 256>>>(b1, dout, n, 0);

    // layer 2: g_o -> h2; agg + ELU -> g_o
    gemm_alpha_kernel<64><<<gemmGrid, 256>>>(nullptr, W2, asr2, adt2, n);
    agg_kernel<<<aggGrid, 256>>>(b2, dout, n, 0);

    // layer 3: g_o -> h3; agg (no ELU) -> d_out
    gemm_alpha_kernel<64><<<gemmGrid, 256>>>(nullptr, W3, asr3, adt3, n);
    agg_kernel<<<aggGrid, 256>>>(b3, dout, n, 1);
}

// round 5
// speedup vs baseline: 2.7154x; 1.0111x over previous
#include <cuda_runtime.h>

#define NN 50000
#define EE 800000
#define ET (EE + NN)
#define CH 64
#define CSR_BLOCKS 592   // 148 SMs x 4 blocks, all co-resident via __launch_bounds__(256,4)

typedef unsigned long long ull;

// ---------------- scratch (static device globals; no allocation) ----------------
__device__ __align__(256) float g_h[(size_t)NN * CH];   // h = X @ W (row-major [N][64])
__device__ __align__(256) float g_o[(size_t)NN * CH];   // aggregated output
__device__ float g_as[NN];               // alpha_src per node
__device__ float g_ad[NN];               // alpha_dst per node
__device__ int   g_deg[NN];
__device__ int   g_cur[NN];              // fill cursor
__device__ int   g_off[NN + 1];
__device__ int   g_bsum[256];
__device__ int   g_ssrc[ET];             // CSR-by-dst: source node of each edge
__device__ unsigned g_barcnt;            // zero-init; self-resetting
__device__ unsigned g_bargen;            // monotonic generation counter

// ---------------- f32x2 packed math helpers ----------------
__device__ __forceinline__ ull pack2(float x, float y) {
    ull r; asm("mov.b64 %0, {%1,%2};" : "=l"(r) : "f"(x), "f"(y)); return r;
}
__device__ __forceinline__ ull fma2(ull a, ull b, ull c) {
    ull d; asm("fma.rn.f32x2 %0, %1, %2, %3;" : "=l"(d) : "l"(a), "l"(b), "l"(c)); return d;
}
__device__ __forceinline__ void unpack2(ull p, float& x, float& y) {
    asm("mov.b64 {%0,%1}, %2;" : "=f"(x), "=f"(y) : "l"(p));
}

// ---------------- software grid barrier (all blocks resident by construction) ----------------
__device__ __forceinline__ void gridbar() {
    __syncthreads();
    __threadfence();                       // release phase writes to L2
    if (threadIdx.x == 0) {
        unsigned gen = *(volatile unsigned*)&g_bargen;
        if (atomicAdd(&g_barcnt, 1u) == (unsigned)(CSR_BLOCKS - 1)) {
            g_barcnt = 0;
            __threadfence();
            atomicAdd(&g_bargen, 1u);      // release generation
        } else {
            while (*(volatile unsigned*)&g_bargen == gen) { }
        }
    }
    __syncthreads();
}

// ---------------- fused CSR build: zero -> count -> scan -> prefix-add -> fill ----------------
__global__ __launch_bounds__(256, 4) void csr_kernel(const int* __restrict__ ei, int E, int n) {
    const int tid = threadIdx.x;
    const int gt = blockIdx.x * 256 + tid;
    const int gstride = CSR_BLOCKS * 256;
    const int tot = E + n;
    const int nbt = (n + 255) / 256;       // 196 scan tiles

    // phase 0: zero degree counters
    for (int i = gt; i < n; i += gstride) g_deg[i] = 0;
    gridbar();

    // phase 1: count in-degree (incl. self-loops)
    for (int e = gt; e < tot; e += gstride) {
        int dst = (e < E) ? ei[E + e] : (e - E);
        atomicAdd(&g_deg[dst], 1);
    }
    gridbar();

    // phase 2: per-tile exclusive scan (tiles 0..nbt-1 on blocks 0..nbt-1)
    if ((int)blockIdx.x < nbt) {
        __shared__ int wsum[8];
        __shared__ int wpre[8];
        int i = blockIdx.x * 256 + tid;
        int lane = tid & 31, wid = tid >> 5;
        int v = (i < n) ? __ldcg(&g_deg[i]) : 0;   // cross-SM data: bypass L1
        int incl = v;
        #pragma unroll
        for (int off = 1; off < 32; off <<= 1) {
            int t = __shfl_up_sync(0xffffffffu, incl, off);
            if (lane >= off) incl += t;
        }
        if (lane == 31) wsum[wid] = incl;
        __syncthreads();
        if (tid == 0) {
            int run = 0;
            #pragma unroll
            for (int w = 0; w < 8; w++) { wpre[w] = run; run += wsum[w]; }
            g_bsum[blockIdx.x] = run;
        }
        __syncthreads();
        if (i < n) g_off[i] = wpre[wid] + incl - v;
    }
    gridbar();

    // phase 3: add tile-sum prefix; init cursors
    if ((int)blockIdx.x < nbt) {
        __shared__ int spre;
        if (tid < 32) {
            int pre = 0, totdeg = 0;
            for (int i = tid; i < nbt; i += 32) {
                int v = __ldcg(&g_bsum[i]);        // written by other blocks
                totdeg += v;
                if (i < (int)blockIdx.x) pre += v;
            }
            #pragma unroll
            for (int o = 16; o; o >>= 1) {
                pre    += __shfl_xor_sync(0xffffffffu, pre, o);
                totdeg += __shfl_xor_sync(0xffffffffu, totdeg, o);
            }
            if (tid == 0) {
                spre = pre;
                if (blockIdx.x == 0) g_off[n] = totdeg;
            }
        }
        __syncthreads();
        int i = blockIdx.x * 256 + tid;
        if (i < n) {
            int v = g_off[i] + spre;               // g_off[i] written by THIS block in phase 2
            g_off[i] = v;
            g_cur[i] = v;
        }
    }
    gridbar();

    // phase 4: fill CSR (cursor atomics live at L2)
    for (int e = gt; e < tot; e += gstride) {
        int src, dst;
        if (e < E) { src = ei[e]; dst = ei[E + e]; }
        else       { src = e - E; dst = src; }
        int p = atomicAdd(&g_cur[dst], 1);
        g_ssrc[p] = src;
    }
}

// ---------------- tiled GEMM (64x64 per block, f32x2 FMA) + fused alpha ----------------
template <int CIN>
__global__ __launch_bounds__(256) void gemm_alpha_kernel(
        const float* __restrict__ Xin, const float* __restrict__ W,
        const float* __restrict__ avs, const float* __restrict__ avd, int n) {
    __shared__ float Xs[64][33];
    __shared__ float Ws[32][64];
    const float* X = Xin ? Xin : g_o;

    int tid = threadIdx.x;
    int tx = tid & 15, ty = tid >> 4;
    int m0 = blockIdx.x * 64;

    ull acc[4][2];
    #pragma unroll
    for (int r = 0; r < 4; r++) { acc[r][0] = pack2(0.f, 0.f); acc[r][1] = pack2(0.f, 0.f); }

    for (int k0 = 0; k0 < CIN; k0 += 32) {
        {
            int r = tid >> 2, kq = (tid & 3) * 8;
            int row = min(m0 + r, n - 1);
            const float4* xp = (const float4*)(X + (size_t)row * CIN + k0 + kq);
            float4 v0 = xp[0], v1 = xp[1];
            Xs[r][kq + 0] = v0.x; Xs[r][kq + 1] = v0.y; Xs[r][kq + 2] = v0.z; Xs[r][kq + 3] = v0.w;
            Xs[r][kq + 4] = v1.x; Xs[r][kq + 5] = v1.y; Xs[r][kq + 6] = v1.z; Xs[r][kq + 7] = v1.w;
        }
        {
            int kk = tid >> 3, c = (tid & 7) * 8;
            const float4* wp = (const float4*)(W + (size_t)(k0 + kk) * CH + c);
            *(float4*)&Ws[kk][c]     = wp[0];
            *(float4*)&Ws[kk][c + 4] = wp[1];
        }
        __syncthreads();

        #pragma unroll
        for (int kk = 0; kk < 32; kk++) {
            float4 wv = *(const float4*)&Ws[kk][tx * 4];
            ull wp0 = pack2(wv.x, wv.y);
            ull wp1 = pack2(wv.z, wv.w);
            #pragma unroll
            for (int r = 0; r < 4; r++) {
                float xv = Xs[ty * 4 + r][kk];
                ull xp = pack2(xv, xv);
                acc[r][0] = fma2(xp, wp0, acc[r][0]);
                acc[r][1] = fma2(xp, wp1, acc[r][1]);
            }
        }
        __syncthreads();
    }

    float c4[4][4];
    #pragma unroll
    for (int r = 0; r < 4; r++) {
        unpack2(acc[r][0], c4[r][0], c4[r][1]);
        unpack2(acc[r][1], c4[r][2], c4[r][3]);
    }

    float4 av = *(const float4*)&avs[tx * 4];
    float4 dv = *(const float4*)&avd[tx * 4];

    #pragma unroll
    for (int r = 0; r < 4; r++) {
        int row = m0 + ty * 4 + r;
        float ps = c4[r][0] * av.x + c4[r][1] * av.y + c4[r][2] * av.z + c4[r][3] * av.w;
        float pd = c4[r][0] * dv.x + c4[r][1] * dv.y + c4[r][2] * dv.z + c4[r][3] * dv.w;
        #pragma unroll
        for (int o = 8; o; o >>= 1) {
            ps += __shfl_xor_sync(0xffffffffu, ps, o, 16);
            pd += __shfl_xor_sync(0xffffffffu, pd, o, 16);
        }
        if (row < n) {
            float4 hv; hv.x = c4[r][0]; hv.y = c4[r][1]; hv.z = c4[r][2]; hv.w = c4[r][3];
            *(float4*)&g_h[(size_t)row * CH + tx * 4] = hv;
            if (tx == 0) { g_as[row] = ps; g_ad[row] = pd; }
        }
    }
}

// ---------------- segment softmax + weighted aggregation ----------------
// One warp per destination node; halves of the warp process 2 edges per iter,
// each half gathering its edge's h row as float4 (16 lanes x 16B = 256B coalesced).
__global__ void agg_kernel(const float* __restrict__ bias,
                           float* __restrict__ dout, int n, int mode) {
    int lane = threadIdx.x & 31;
    int half = lane >> 4;
    int q = lane & 15;
    int gw = (blockIdx.x * blockDim.x + threadIdx.x) >> 5;
    int nw = (gridDim.x * blockDim.x) >> 5;
    float* out = mode ? dout : g_o;
    const float4* h4 = (const float4*)g_h;

    for (int d = gw; d < n; d += nw) {
        int beg = g_off[d], end = g_off[d + 1];
        float adv = g_ad[d];

        float4 acc; acc.x = acc.y = acc.z = acc.w = 0.f;
        float denp = 0.f;
        for (int base = beg; base < end; base += 32) {
            int j = base + lane;
            int s = 0;
            float w = 0.f;
            if (j < end) {
                s = g_ssrc[j];
                float e = g_as[s] + adv;
                e = e > 0.f ? e : 0.2f * e;
                w = __expf(e);
            }
            denp += w;
            int cnt = min(32, end - base);
            #pragma unroll 4
            for (int k = 0; k < cnt; k += 2) {
                int e = k + half;
                int   sk = __shfl_sync(0xffffffffu, s, e & 31);
                float wk = __shfl_sync(0xffffffffu, w, e & 31);
                if (e >= cnt) wk = 0.f;               // odd-count overhang on half 1
                float4 hv = h4[(size_t)sk * 16 + q];
                acc.x = fmaf(wk, hv.x, acc.x);
                acc.y = fmaf(wk, hv.y, acc.y);
                acc.z = fmaf(wk, hv.z, acc.z);
                acc.w = fmaf(wk, hv.w, acc.w);
            }
        }
        // combine the two halves
        acc.x += __shfl_xor_sync(0xffffffffu, acc.x, 16);
        acc.y += __shfl_xor_sync(0xffffffffu, acc.y, 16);
        acc.z += __shfl_xor_sync(0xffffffffu, acc.z, 16);
        acc.w += __shfl_xor_sync(0xffffffffu, acc.w, 16);
        float den = denp;
        #pragma unroll
        for (int o = 16; o; o >>= 1) den += __shfl_xor_sync(0xffffffffu, den, o);

        if (half == 0) {
            float inv = 1.f / den;
            float4 bv = ((const float4*)bias)[q];
            float4 ov;
            ov.x = acc.x * inv + bv.x;
            ov.y = acc.y * inv + bv.y;
            ov.z = acc.z * inv + bv.z;
            ov.w = acc.w * inv + bv.w;
            if (mode == 0) {  // ELU for layers 1 & 2
                ov.x = ov.x > 0.f ? ov.x : (__expf(ov.x) - 1.f);
                ov.y = ov.y > 0.f ? ov.y : (__expf(ov.y) - 1.f);
                ov.z = ov.z > 0.f ? ov.z : (__expf(ov.z) - 1.f);
                ov.w = ov.w > 0.f ? ov.w : (__expf(ov.w) - 1.f);
            }
            ((float4*)out)[(size_t)d * 16 + q] = ov;
        }
    }
}

// ---------------- launch ----------------
extern "C" void kernel_launch(void* const* d_in, const int* in_sizes, int n_in,
                              void* d_out, int out_size) {
    const float* x     = (const float*)d_in[0];
    const int*   ei    = (const int*)d_in[1];
    const float* W1    = (const float*)d_in[2];
    const float* asr1  = (const float*)d_in[3];
    const float* adt1  = (const float*)d_in[4];
    const float* b1    = (const float*)d_in[5];
    const float* W2    = (const float*)d_in[6];
    const float* asr2  = (const float*)d_in[7];
    const float* adt2  = (const float*)d_in[8];
    const float* b2    = (const float*)d_in[9];
    const float* W3    = (const float*)d_in[10];
    const float* asr3  = (const float*)d_in[11];
    const float* adt3  = (const float*)d_in[12];
    const float* b3    = (const float*)d_in[13];

    int n = in_sizes[0] / 128;   // 50000
    int E = in_sizes[1] / 2;     // 800000
    float* dout = (float*)d_out;

    // fused CSR build (single kernel, software grid barriers)
    csr_kernel<<<CSR_BLOCKS, 256>>>(ei, E, n);

    int aggGrid = (n * 32 + 255) / 256;
    int gemmGrid = (n + 63) / 64;

    // layer 1: x[N,128] -> h1; agg + ELU -> g_o
    gemm_alpha_kernel<128><<<gemmGrid, 256>>>(x, W1, asr1, adt1, n);
    agg_kernel<<<aggGrid, 256>>>(b1, dout, n, 0);

    // layer 2: g_o -> h2; agg + ELU -> g_o
    gemm_alpha_kernel<64><<<gemmGrid, 256>>>(nullptr, W2, asr2, adt2, n);
    agg_kernel<<<aggGrid, 256>>>(b2, dout, n, 0);

    // layer 3: g_o -> h3; agg (no ELU) -> d_out
    gemm_alpha_kernel<64><<<gemmGrid, 256>>>(nullptr, W3, asr3, adt3, n);
    agg_kernel<<<aggGrid, 256>>>(b3, dout, n, 1);
}

// round 7
// speedup vs baseline: 2.8087x; 1.0344x over previous
#include <cuda_runtime.h>

#define NN 50000
#define EE 800000
#define ET (EE + NN)
#define CH 64
#define CSR_BLOCKS 592   // 148 SMs x 4 blocks, all co-resident via __launch_bounds__(256,4)

typedef unsigned long long ull;

// ---------------- scratch (static device globals; no allocation) ----------------
__device__ __align__(256) float g_h[(size_t)NN * CH];   // h = X @ W (row-major [N][64])
__device__ __align__(256) float g_o[(size_t)NN * CH];   // aggregated output
__device__ float g_as[NN];               // alpha_src per node
__device__ float g_ad[NN];               // alpha_dst per node
__device__ int   g_deg[NN];
__device__ int   g_cur[NN];              // fill cursor
__device__ int   g_off[NN + 1];
__device__ int   g_bsum[256];
__device__ int   g_ssrc[ET];             // CSR-by-dst: source node of each edge
__device__ unsigned g_barcnt;            // zero-init; self-resetting
__device__ unsigned g_bargen;            // monotonic generation counter

// ---------------- f32x2 packed math helpers ----------------
__device__ __forceinline__ ull pack2(float x, float y) {
    ull r; asm("mov.b64 %0, {%1,%2};" : "=l"(r) : "f"(x), "f"(y)); return r;
}
__device__ __forceinline__ ull fma2(ull a, ull b, ull c) {
    ull d; asm("fma.rn.f32x2 %0, %1, %2, %3;" : "=l"(d) : "l"(a), "l"(b), "l"(c)); return d;
}
__device__ __forceinline__ void unpack2(ull p, float& x, float& y) {
    asm("mov.b64 {%0,%1}, %2;" : "=f"(x), "=f"(y) : "l"(p));
}

// ---------------- software grid barrier (all blocks resident by construction) ----------------
__device__ __forceinline__ void gridbar() {
    __syncthreads();
    __threadfence();
    if (threadIdx.x == 0) {
        unsigned gen = *(volatile unsigned*)&g_bargen;
        if (atomicAdd(&g_barcnt, 1u) == (unsigned)(CSR_BLOCKS - 1)) {
            g_barcnt = 0;
            __threadfence();
            atomicAdd(&g_bargen, 1u);
        } else {
            while (*(volatile unsigned*)&g_bargen == gen) { }
        }
    }
    __syncthreads();
}

// ---------------- fused CSR build: zero -> count -> scan -> prefix-add -> fill ----------------
__global__ __launch_bounds__(256, 4) void csr_kernel(const int* __restrict__ ei, int E, int n) {
    const int tid = threadIdx.x;
    const int gt = blockIdx.x * 256 + tid;
    const int gstride = CSR_BLOCKS * 256;
    const int tot = E + n;
    const int nbt = (n + 255) / 256;       // 196 scan tiles

    for (int i = gt; i < n; i += gstride) g_deg[i] = 0;
    gridbar();

    for (int e = gt; e < tot; e += gstride) {
        int dst = (e < E) ? ei[E + e] : (e - E);
        atomicAdd(&g_deg[dst], 1);
    }
    gridbar();

    if ((int)blockIdx.x < nbt) {
        __shared__ int wsum[8];
        __shared__ int wpre[8];
        int i = blockIdx.x * 256 + tid;
        int lane = tid & 31, wid = tid >> 5;
        int v = (i < n) ? __ldcg(&g_deg[i]) : 0;
        int incl = v;
        #pragma unroll
        for (int off = 1; off < 32; off <<= 1) {
            int t = __shfl_up_sync(0xffffffffu, incl, off);
            if (lane >= off) incl += t;
        }
        if (lane == 31) wsum[wid] = incl;
        __syncthreads();
        if (tid == 0) {
            int run = 0;
            #pragma unroll
            for (int w = 0; w < 8; w++) { wpre[w] = run; run += wsum[w]; }
            g_bsum[blockIdx.x] = run;
        }
        __syncthreads();
        if (i < n) g_off[i] = wpre[wid] + incl - v;
    }
    gridbar();

    if ((int)blockIdx.x < nbt) {
        __shared__ int spre;
        if (tid < 32) {
            int pre = 0, totdeg = 0;
            for (int i = tid; i < nbt; i += 32) {
                int v = __ldcg(&g_bsum[i]);
                totdeg += v;
                if (i < (int)blockIdx.x) pre += v;
            }
            #pragma unroll
            for (int o = 16; o; o >>= 1) {
                pre    += __shfl_xor_sync(0xffffffffu, pre, o);
                totdeg += __shfl_xor_sync(0xffffffffu, totdeg, o);
            }
            if (tid == 0) {
                spre = pre;
                if (blockIdx.x == 0) g_off[n] = totdeg;
            }
        }
        __syncthreads();
        int i = blockIdx.x * 256 + tid;
        if (i < n) {
            int v = g_off[i] + spre;
            g_off[i] = v;
            g_cur[i] = v;
        }
    }
    gridbar();

    for (int e = gt; e < tot; e += gstride) {
        int src, dst;
        if (e < E) { src = ei[e]; dst = ei[E + e]; }
        else       { src = e - E; dst = src; }
        int p = atomicAdd(&g_cur[dst], 1);
        g_ssrc[p] = src;
    }
}

// ---------------- tiled GEMM (64x64 per block, f32x2 FMA) + fused alpha ----------------
// Xs stored k-major [32][72]: per k-step each thread does 2x LDS.128 for 8 FFMA2.
template <int CIN>
__global__ __launch_bounds__(256) void gemm_alpha_kernel(
        const float* __restrict__ Xin, const float* __restrict__ W,
        const float* __restrict__ avs, const float* __restrict__ avd, int n) {
    __shared__ float Xs[32][72];   // [k][m], pad 8 keeps float4 alignment
    __shared__ float Ws[32][64];   // [k][c]
    const float* X = Xin ? Xin : g_o;

    int tid = threadIdx.x;
    int tx = tid & 15, ty = tid >> 4;
    int m0 = blockIdx.x * 64;

    ull acc[4][2];
    #pragma unroll
    for (int r = 0; r < 4; r++) { acc[r][0] = pack2(0.f, 0.f); acc[r][1] = pack2(0.f, 0.f); }

    for (int k0 = 0; k0 < CIN; k0 += 32) {
        // stage X tile transposed: thread (r = tid>>2, kq = (tid&3)*8) loads 8 k-consecutive
        {
            int r = tid >> 2, kq = (tid & 3) * 8;
            int row = min(m0 + r, n - 1);
            const float4* xp = (const float4*)(X + (size_t)row * CIN + k0 + kq);
            float4 v0 = xp[0], v1 = xp[1];
            Xs[kq + 0][r] = v0.x; Xs[kq + 1][r] = v0.y; Xs[kq + 2][r] = v0.z; Xs[kq + 3][r] = v0.w;
            Xs[kq + 4][r] = v1.x; Xs[kq + 5][r] = v1.y; Xs[kq + 6][r] = v1.z; Xs[kq + 7][r] = v1.w;
        }
        // stage W tile [32][64]
        {
            int kk = tid >> 3, c = (tid & 7) * 8;
            const float4* wp = (const float4*)(W + (size_t)(k0 + kk) * CH + c);
            *(float4*)&Ws[kk][c]     = wp[0];
            *(float4*)&Ws[kk][c + 4] = wp[1];
        }
        __syncthreads();

        #pragma unroll
        for (int kk = 0; kk < 32; kk++) {
            float4 xv = *(const float4*)&Xs[kk][ty * 4];   // 4 rows' x (2 distinct addrs/warp)
            float4 wv = *(const float4*)&Ws[kk][tx * 4];   // 4 cols' w
            ull wp0 = pack2(wv.x, wv.y);
            ull wp1 = pack2(wv.z, wv.w);
            ull xp0 = pack2(xv.x, xv.x);
            ull xp1 = pack2(xv.y, xv.y);
            ull xp2 = pack2(xv.z, xv.z);
            ull xp3 = pack2(xv.w, xv.w);
            acc[0][0] = fma2(xp0, wp0, acc[0][0]);
            acc[0][1] = fma2(xp0, wp1, acc[0][1]);
            acc[1][0] = fma2(xp1, wp0, acc[1][0]);
            acc[1][1] = fma2(xp1, wp1, acc[1][1]);
            acc[2][0] = fma2(xp2, wp0, acc[2][0]);
            acc[2][1] = fma2(xp2, wp1, acc[2][1]);
            acc[3][0] = fma2(xp3, wp0, acc[3][0]);
            acc[3][1] = fma2(xp3, wp1, acc[3][1]);
        }
        __syncthreads();
    }

    float c4[4][4];
    #pragma unroll
    for (int r = 0; r < 4; r++) {
        unpack2(acc[r][0], c4[r][0], c4[r][1]);
        unpack2(acc[r][1], c4[r][2], c4[r][3]);
    }

    float4 av = *(const float4*)&avs[tx * 4];
    float4 dv = *(const float4*)&avd[tx * 4];

    #pragma unroll
    for (int r = 0; r < 4; r++) {
        int row = m0 + ty * 4 + r;
        float ps = c4[r][0] * av.x + c4[r][1] * av.y + c4[r][2] * av.z + c4[r][3] * av.w;
        float pd = c4[r][0] * dv.x + c4[r][1] * dv.y + c4[r][2] * dv.z + c4[r][3] * dv.w;
        #pragma unroll
        for (int o = 8; o; o >>= 1) {
            ps += __shfl_xor_sync(0xffffffffu, ps, o, 16);
            pd += __shfl_xor_sync(0xffffffffu, pd, o, 16);
        }
        if (row < n) {
            float4 hv; hv.x = c4[r][0]; hv.y = c4[r][1]; hv.z = c4[r][2]; hv.w = c4[r][3];
            *(float4*)&g_h[(size_t)row * CH + tx * 4] = hv;
            if (tx == 0) { g_as[row] = ps; g_ad[row] = pd; }
        }
    }
}

// ---------------- segment softmax + weighted aggregation ----------------
// One warp per destination; halves process 2 edges/iter with float4 gathers.
// Dual accumulators break the fmaf dependency chain between iterations.
__global__ void agg_kernel(const float* __restrict__ bias,
                           float* __restrict__ dout, int n, int mode) {
    int lane = threadIdx.x & 31;
    int half = lane >> 4;
    int q = lane & 15;
    int gw = (blockIdx.x * blockDim.x + threadIdx.x) >> 5;
    int nw = (gridDim.x * blockDim.x) >> 5;
    float* out = mode ? dout : g_o;
    const float4* h4 = (const float4*)g_h;

    for (int d = gw; d < n; d += nw) {
        int beg = g_off[d], end = g_off[d + 1];
        float adv = g_ad[d];

        float4 accA; accA.x = accA.y = accA.z = accA.w = 0.f;
        float4 accB; accB.x = accB.y = accB.z = accB.w = 0.f;
        float denp = 0.f;
        for (int base = beg; base < end; base += 32) {
            int j = base + lane;
            int s = 0;
            float w = 0.f;
            if (j < end) {
                s = g_ssrc[j];
                float e = g_as[s] + adv;
                e = e > 0.f ? e : 0.2f * e;
                w = __expf(e);
            }
            denp += w;
            int cnt = min(32, end - base);
            #pragma unroll 4
            for (int k = 0; k < cnt; k += 4) {
                int e0 = k + half;
                int e1 = k + 2 + half;
                int   s0 = __shfl_sync(0xffffffffu, s, e0 & 31);
                float w0 = __shfl_sync(0xffffffffu, w, e0 & 31);
                int   s1 = __shfl_sync(0xffffffffu, s, e1 & 31);
                float w1 = __shfl_sync(0xffffffffu, w, e1 & 31);
                if (e0 >= cnt) w0 = 0.f;
                if (e1 >= cnt) w1 = 0.f;
                float4 h0 = h4[(size_t)s0 * 16 + q];
                float4 h1 = h4[(size_t)s1 * 16 + q];
                accA.x = fmaf(w0, h0.x, accA.x);
                accA.y = fmaf(w0, h0.y, accA.y);
                accA.z = fmaf(w0, h0.z, accA.z);
                accA.w = fmaf(w0, h0.w, accA.w);
                accB.x = fmaf(w1, h1.x, accB.x);
                accB.y = fmaf(w1, h1.y, accB.y);
                accB.z = fmaf(w1, h1.z, accB.z);
                accB.w = fmaf(w1, h1.w, accB.w);
            }
        }
        float4 acc;
        acc.x = accA.x + accB.x;
        acc.y = accA.y + accB.y;
        acc.z = accA.z + accB.z;
        acc.w = accA.w + accB.w;
        acc.x += __shfl_xor_sync(0xffffffffu, acc.x, 16);
        acc.y += __shfl_xor_sync(0xffffffffu, acc.y, 16);
        acc.z += __shfl_xor_sync(0xffffffffu, acc.z, 16);
        acc.w += __shfl_xor_sync(0xffffffffu, acc.w, 16);
        float den = denp;
        #pragma unroll
        for (int o = 16; o; o >>= 1) den += __shfl_xor_sync(0xffffffffu, den, o);

        if (half == 0) {
            float inv = 1.f / den;
            float4 bv = ((const float4*)bias)[q];
            float4 ov;
            ov.x = acc.x * inv + bv.x;
            ov.y = acc.y * inv + bv.y;
            ov.z = acc.z * inv + bv.z;
            ov.w = acc.w * inv + bv.w;
            if (mode == 0) {  // ELU for layers 1 & 2
                ov.x = ov.x > 0.f ? ov.x : (__expf(ov.x) - 1.f);
                ov.y = ov.y > 0.f ? ov.y : (__expf(ov.y) - 1.f);
                ov.z = ov.z > 0.f ? ov.z : (__expf(ov.z) - 1.f);
                ov.w = ov.w > 0.f ? ov.w : (__expf(ov.w) - 1.f);
            }
            ((float4*)out)[(size_t)d * 16 + q] = ov;
        }
    }
}

// ---------------- launch ----------------
extern "C" void kernel_launch(void* const* d_in, const int* in_sizes, int n_in,
                              void* d_out, int out_size) {
    const float* x     = (const float*)d_in[0];
    const int*   ei    = (const int*)d_in[1];
    const float* W1    = (const float*)d_in[2];
    const float* asr1  = (const float*)d_in[3];
    const float* adt1  = (const float*)d_in[4];
    const float* b1    = (const float*)d_in[5];
    const float* W2    = (const float*)d_in[6];
    const float* asr2  = (const float*)d_in[7];
    const float* adt2  = (const float*)d_in[8];
    const float* b2    = (const float*)d_in[9];
    const float* W3    = (const float*)d_in[10];
    const float* asr3  = (const float*)d_in[11];
    const float* adt3  = (const float*)d_in[12];
    const float* b3    = (const float*)d_in[13];

    int n = in_sizes[0] / 128;   // 50000
    int E = in_sizes[1] / 2;     // 800000
    float* dout = (float*)d_out;

    csr_kernel<<<CSR_BLOCKS, 256>>>(ei, E, n);

    int aggGrid = (n * 32 + 255) / 256;
    int gemmGrid = (n + 63) / 64;

    gemm_alpha_kernel<128><<<gemmGrid, 256>>>(x, W1, asr1, adt1, n);
    agg_kernel<<<aggGrid, 256>>>(b1, dout, n, 0);

    gemm_alpha_kernel<64><<<gemmGrid, 256>>>(nullptr, W2, asr2, adt2, n);
    agg_kernel<<<aggGrid, 256>>>(b2, dout, n, 0);

    gemm_alpha_kernel<64><<<gemmGrid, 256>>>(nullptr, W3, asr3, adt3, n);
    agg_kernel<<<aggGrid, 256>>>(b3, dout, n, 1);
}

// round 9
// speedup vs baseline: 2.8092x; 1.0002x over previous
#include <cuda_runtime.h>
#include <cuda_fp16.h>

#define NN 50000
#define EE 800000
#define ET (EE + NN)
#define CH 64
#define CSR_BLOCKS 592   // 148 SMs x 4 blocks, all co-resident via __launch_bounds__(256,4)

typedef unsigned long long ull;

// ---------------- scratch (static device globals; no allocation) ----------------
__device__ __align__(256) __half g_h[(size_t)NN * CH];  // h = X @ W, fp16 (row = 128B)
__device__ __align__(256) float  g_o[(size_t)NN * CH];  // aggregated output (fp32)
__device__ float g_as[NN];               // alpha_src per node
__device__ float g_ad[NN];               // alpha_dst per node
__device__ int   g_deg[NN];
__device__ int   g_cur[NN];              // fill cursor
__device__ int   g_off[NN + 1];
__device__ int   g_bsum[256];
__device__ int   g_ssrc[ET];             // CSR-by-dst: source node of each edge
__device__ unsigned g_barcnt;            // zero-init; self-resetting
__device__ unsigned g_bargen;            // monotonic generation counter

// ---------------- f32x2 packed math helpers ----------------
__device__ __forceinline__ ull pack2(float x, float y) {
    ull r; asm("mov.b64 %0, {%1,%2};" : "=l"(r) : "f"(x), "f"(y)); return r;
}
__device__ __forceinline__ ull fma2(ull a, ull b, ull c) {
    ull d; asm("fma.rn.f32x2 %0, %1, %2, %3;" : "=l"(d) : "l"(a), "l"(b), "l"(c)); return d;
}
__device__ __forceinline__ void unpack2(ull p, float& x, float& y) {
    asm("mov.b64 {%0,%1}, %2;" : "=f"(x), "=f"(y) : "l"(p));
}

// ---------------- software grid barrier ----------------
__device__ __forceinline__ void gridbar() {
    __syncthreads();
    __threadfence();
    if (threadIdx.x == 0) {
        unsigned gen = *(volatile unsigned*)&g_bargen;
        if (atomicAdd(&g_barcnt, 1u) == (unsigned)(CSR_BLOCKS - 1)) {
            g_barcnt = 0;
            __threadfence();
            atomicAdd(&g_bargen, 1u);
        } else {
            while (*(volatile unsigned*)&g_bargen == gen) { }
        }
    }
    __syncthreads();
}

// ---------------- fused CSR build: zero -> count -> scan -> prefix-add -> fill ----------------
__global__ __launch_bounds__(256, 4) void csr_kernel(const int* __restrict__ ei, int E, int n) {
    const int tid = threadIdx.x;
    const int gt = blockIdx.x * 256 + tid;
    const int gstride = CSR_BLOCKS * 256;
    const int tot = E + n;
    const int nbt = (n + 255) / 256;       // 196 scan tiles

    for (int i = gt; i < n; i += gstride) g_deg[i] = 0;
    gridbar();

    for (int e = gt; e < tot; e += gstride) {
        int dst = (e < E) ? ei[E + e] : (e - E);
        atomicAdd(&g_deg[dst], 1);
    }
    gridbar();

    if ((int)blockIdx.x < nbt) {
        __shared__ int wsum[8];
        __shared__ int wpre[8];
        int i = blockIdx.x * 256 + tid;
        int lane = tid & 31, wid = tid >> 5;
        int v = (i < n) ? __ldcg(&g_deg[i]) : 0;
        int incl = v;
        #pragma unroll
        for (int off = 1; off < 32; off <<= 1) {
            int t = __shfl_up_sync(0xffffffffu, incl, off);
            if (lane >= off) incl += t;
        }
        if (lane == 31) wsum[wid] = incl;
        __syncthreads();
        if (tid == 0) {
            int run = 0;
            #pragma unroll
            for (int w = 0; w < 8; w++) { wpre[w] = run; run += wsum[w]; }
            g_bsum[blockIdx.x] = run;
        }
        __syncthreads();
        if (i < n) g_off[i] = wpre[wid] + incl - v;
    }
    gridbar();

    if ((int)blockIdx.x < nbt) {
        __shared__ int spre;
        if (tid < 32) {
            int pre = 0, totdeg = 0;
            for (int i = tid; i < nbt; i += 32) {
                int v = __ldcg(&g_bsum[i]);
                totdeg += v;
                if (i < (int)blockIdx.x) pre += v;
            }
            #pragma unroll
            for (int o = 16; o; o >>= 1) {
                pre    += __shfl_xor_sync(0xffffffffu, pre, o);
                totdeg += __shfl_xor_sync(0xffffffffu, totdeg, o);
            }
            if (tid == 0) {
                spre = pre;
                if (blockIdx.x == 0) g_off[n] = totdeg;
            }
        }
        __syncthreads();
        int i = blockIdx.x * 256 + tid;
        if (i < n) {
            int v = g_off[i] + spre;
            g_off[i] = v;
            g_cur[i] = v;
        }
    }
    gridbar();

    for (int e = gt; e < tot; e += gstride) {
        int src, dst;
        if (e < E) { src = ei[e]; dst = ei[E + e]; }
        else       { src = e - E; dst = src; }
        int p = atomicAdd(&g_cur[dst], 1);
        g_ssrc[p] = src;
    }
}

// ---------------- tiled GEMM (64x64 per block, f32x2 FMA) + fused alpha ----------------
template <int CIN>
__global__ __launch_bounds__(256) void gemm_alpha_kernel(
        const float* __restrict__ Xin, const float* __restrict__ W,
        const float* __restrict__ avs, const float* __restrict__ avd, int n) {
    __shared__ float Xs[32][72];   // [k][m]
    __shared__ float Ws[32][64];   // [k][c]
    const float* X = Xin ? Xin : g_o;

    int tid = threadIdx.x;
    int tx = tid & 15, ty = tid >> 4;
    int m0 = blockIdx.x * 64;

    ull acc[4][2];
    #pragma unroll
    for (int r = 0; r < 4; r++) { acc[r][0] = pack2(0.f, 0.f); acc[r][1] = pack2(0.f, 0.f); }

    for (int k0 = 0; k0 < CIN; k0 += 32) {
        {
            int r = tid >> 2, kq = (tid & 3) * 8;
            int row = min(m0 + r, n - 1);
            const float4* xp = (const float4*)(X + (size_t)row * CIN + k0 + kq);
            float4 v0 = xp[0], v1 = xp[1];
            Xs[kq + 0][r] = v0.x; Xs[kq + 1][r] = v0.y; Xs[kq + 2][r] = v0.z; Xs[kq + 3][r] = v0.w;
            Xs[kq + 4][r] = v1.x; Xs[kq + 5][r] = v1.y; Xs[kq + 6][r] = v1.z; Xs[kq + 7][r] = v1.w;
        }
        {
            int kk = tid >> 3, c = (tid & 7) * 8;
            const float4* wp = (const float4*)(W + (size_t)(k0 + kk) * CH + c);
            *(float4*)&Ws[kk][c]     = wp[0];
            *(float4*)&Ws[kk][c + 4] = wp[1];
        }
        __syncthreads();

        #pragma unroll
        for (int kk = 0; kk < 32; kk++) {
            float4 xv = *(const float4*)&Xs[kk][ty * 4];
            float4 wv = *(const float4*)&Ws[kk][tx * 4];
            ull wp0 = pack2(wv.x, wv.y);
            ull wp1 = pack2(wv.z, wv.w);
            ull xp0 = pack2(xv.x, xv.x);
            ull xp1 = pack2(xv.y, xv.y);
            ull xp2 = pack2(xv.z, xv.z);
            ull xp3 = pack2(xv.w, xv.w);
            acc[0][0] = fma2(xp0, wp0, acc[0][0]);
            acc[0][1] = fma2(xp0, wp1, acc[0][1]);
            acc[1][0] = fma2(xp1, wp0, acc[1][0]);
            acc[1][1] = fma2(xp1, wp1, acc[1][1]);
            acc[2][0] = fma2(xp2, wp0, acc[2][0]);
            acc[2][1] = fma2(xp2, wp1, acc[2][1]);
            acc[3][0] = fma2(xp3, wp0, acc[3][0]);
            acc[3][1] = fma2(xp3, wp1, acc[3][1]);
        }
        __syncthreads();
    }

    float c4[4][4];
    #pragma unroll
    for (int r = 0; r < 4; r++) {
        unpack2(acc[r][0], c4[r][0], c4[r][1]);
        unpack2(acc[r][1], c4[r][2], c4[r][3]);
    }

    float4 av = *(const float4*)&avs[tx * 4];
    float4 dv = *(const float4*)&avd[tx * 4];

    #pragma unroll
    for (int r = 0; r < 4; r++) {
        int row = m0 + ty * 4 + r;
        float ps = c4[r][0] * av.x + c4[r][1] * av.y + c4[r][2] * av.z + c4[r][3] * av.w;
        float pd = c4[r][0] * dv.x + c4[r][1] * dv.y + c4[r][2] * dv.z + c4[r][3] * dv.w;
        #pragma unroll
        for (int o = 8; o; o >>= 1) {
            ps += __shfl_xor_sync(0xffffffffu, ps, o, 16);
            pd += __shfl_xor_sync(0xffffffffu, pd, o, 16);
        }
        if (row < n) {
            // pack 4 fp32 -> 4 fp16, single 8B store (h row = 128B)
            __half2 p0 = __floats2half2_rn(c4[r][0], c4[r][1]);
            __half2 p1 = __floats2half2_rn(c4[r][2], c4[r][3]);
            union { __half2 h[2]; uint2 u; } pk;
            pk.h[0] = p0; pk.h[1] = p1;
            *(uint2*)((char*)g_h + ((size_t)row << 7) + (tx << 3)) = pk.u;
            if (tx == 0) { g_as[row] = ps; g_ad[row] = pd; }
        }
    }
}

// ---------------- segment softmax + weighted aggregation (fp16 gather) ----------------
// One warp per destination. Quarter-warp (8 lanes) per edge: 8 x LDG.128 = 128B row,
// 4 edges in flight per warp. fp32 accumulation; quarters combined via shfl.
__global__ void agg_kernel(const float* __restrict__ bias,
                           float* __restrict__ dout, int n, int mode) {
    int lane = threadIdx.x & 31;
    int qid = lane >> 3;          // quarter 0..3
    int q = lane & 7;             // lane within quarter -> channels q*8..q*8+7
    int gw = (blockIdx.x * blockDim.x + threadIdx.x) >> 5;
    int nw = (gridDim.x * blockDim.x) >> 5;
    float* out = mode ? dout : g_o;

    for (int d = gw; d < n; d += nw) {
        int beg = g_off[d], end = g_off[d + 1];
        float adv = g_ad[d];

        float acc[8];
        #pragma unroll
        for (int i = 0; i < 8; i++) acc[i] = 0.f;
        float denp = 0.f;

        for (int base = beg; base < end; base += 32) {
            int j = base + lane;
            int s = 0;
            float w = 0.f;
            if (j < end) {
                s = g_ssrc[j];
                float e = g_as[s] + adv;
                e = e > 0.f ? e : 0.2f * e;
                w = __expf(e);
            }
            denp += w;
            int cnt = min(32, end - base);
            #pragma unroll 4
            for (int k = 0; k < cnt; k += 4) {
                int e = k + qid;
                int   sk = __shfl_sync(0xffffffffu, s, e & 31);
                float wk = __shfl_sync(0xffffffffu, w, e & 31);
                if (e >= cnt) wk = 0.f;
                uint4 u = *(const uint4*)((const char*)g_h + ((size_t)sk << 7) + (q << 4));
                float2 f0 = __half22float2(*(__half2*)&u.x);
                float2 f1 = __half22float2(*(__half2*)&u.y);
                float2 f2 = __half22float2(*(__half2*)&u.z);
                float2 f3 = __half22float2(*(__half2*)&u.w);
                acc[0] = fmaf(wk, f0.x, acc[0]);
                acc[1] = fmaf(wk, f0.y, acc[1]);
                acc[2] = fmaf(wk, f1.x, acc[2]);
                acc[3] = fmaf(wk, f1.y, acc[3]);
                acc[4] = fmaf(wk, f2.x, acc[4]);
                acc[5] = fmaf(wk, f2.y, acc[5]);
                acc[6] = fmaf(wk, f3.x, acc[6]);
                acc[7] = fmaf(wk, f3.y, acc[7]);
            }
        }
        // combine the 4 quarters (lanes with same q sum across qid)
        #pragma unroll
        for (int i = 0; i < 8; i++) {
            acc[i] += __shfl_xor_sync(0xffffffffu, acc[i], 8);
            acc[i] += __shfl_xor_sync(0xffffffffu, acc[i], 16);
        }
        float den = denp;
        #pragma unroll
        for (int o = 16; o; o >>= 1) den += __shfl_xor_sync(0xffffffffu, den, o);

        if (qid == 0) {   // lanes 0..7 write channels q*8..q*8+7
            float inv = 1.f / den;
            const float4* b4 = (const float4*)bias;
            float4 bv0 = b4[q * 2], bv1 = b4[q * 2 + 1];
            float4 o0, o1;
            o0.x = acc[0] * inv + bv0.x;
            o0.y = acc[1] * inv + bv0.y;
            o0.z = acc[2] * inv + bv0.z;
            o0.w = acc[3] * inv + bv0.w;
            o1.x = acc[4] * inv + bv1.x;
            o1.y = acc[5] * inv + bv1.y;
            o1.z = acc[6] * inv + bv1.z;
            o1.w = acc[7] * inv + bv1.w;
            if (mode == 0) {  // ELU for layers 1 & 2
                o0.x = o0.x > 0.f ? o0.x : (__expf(o0.x) - 1.f);
                o0.y = o0.y > 0.f ? o0.y : (__expf(o0.y) - 1.f);
                o0.z = o0.z > 0.f ? o0.z : (__expf(o0.z) - 1.f);
                o0.w = o0.w > 0.f ? o0.w : (__expf(o0.w) - 1.f);
                o1.x = o1.x > 0.f ? o1.x : (__expf(o1.x) - 1.f);
                o1.y = o1.y > 0.f ? o1.y : (__expf(o1.y) - 1.f);
                o1.z = o1.z > 0.f ? o1.z : (__expf(o1.z) - 1.f);
                o1.w = o1.w > 0.f ? o1.w : (__expf(o1.w) - 1.f);
            }
            float4* orow = (float4*)(out + (size_t)d * CH);
            orow[q * 2]     = o0;
            orow[q * 2 + 1] = o1;
        }
    }
}

// ---------------- launch ----------------
extern "C" void kernel_launch(void* const* d_in, const int* in_sizes, int n_in,
                              void* d_out, int out_size) {
    const float* x     = (const float*)d_in[0];
    const int*   ei    = (const int*)d_in[1];
    const float* W1    = (const float*)d_in[2];
    const float* asr1  = (const float*)d_in[3];
    const float* adt1  = (const float*)d_in[4];
    const float* b1    = (const float*)d_in[5];
    const float* W2    = (const float*)d_in[6];
    const float* asr2  = (const float*)d_in[7];
    const float* adt2  = (const float*)d_in[8];
    const float* b2    = (const float*)d_in[9];
    const float* W3    = (const float*)d_in[10];
    const float* asr3  = (const float*)d_in[11];
    const float* adt3  = (const float*)d_in[12];
    const float* b3    = (const float*)d_in[13];

    int n = in_sizes[0] / 128;   // 50000
    int E = in_sizes[1] / 2;     // 800000
    float* dout = (float*)d_out;

    csr_kernel<<<CSR_BLOCKS, 256>>>(ei, E, n);

    int aggGrid = (n * 32 + 255) / 256;
    int gemmGrid = (n + 63) / 64;

    gemm_alpha_kernel<128><<<gemmGrid, 256>>>(x, W1, asr1, adt1, n);
    agg_kernel<<<aggGrid, 256>>>(b1, dout, n, 0);

    gemm_alpha_kernel<64><<<gemmGrid, 256>>>(nullptr, W2, asr2, adt2, n);
    agg_kernel<<<aggGrid, 256>>>(b2, dout, n, 0);

    gemm_alpha_kernel<64><<<gemmGrid, 256>>>(nullptr, W3, asr3, adt3, n);
    agg_kernel<<<aggGrid, 256>>>(b3, dout, n, 1);
}

// round 10
// speedup vs baseline: 2.8341x; 1.0089x over previous
#include <cuda_runtime.h>
#include <cuda_fp16.h>

#define NN 50000
#define EE 800000
#define ET (EE + NN)
#define CH 64
#define CSR_BLOCKS 592   // 148 SMs x 4 blocks, all co-resident via __launch_bounds__(256,4)

typedef unsigned long long ull;

// ---------------- scratch (static device globals; no allocation) ----------------
__device__ __align__(256) __half g_h[(size_t)NN * CH];  // h = X @ W, fp16 (row = 128B)
__device__ __align__(256) float  g_o[(size_t)NN * CH];  // aggregated output (fp32)
__device__ float g_as[NN];               // alpha_src per node
__device__ float g_ad[NN];               // alpha_dst per node
__device__ int   g_deg[NN];
__device__ int   g_cur[NN];              // fill cursor
__device__ int   g_off[NN + 1];
__device__ int   g_bsum[256];
__device__ int   g_ssrc[ET];             // CSR-by-dst: source node of each edge
__device__ unsigned g_barcnt;
__device__ unsigned g_bargen;

// ---------------- f32x2 packed math helpers ----------------
__device__ __forceinline__ ull pack2(float x, float y) {
    ull r; asm("mov.b64 %0, {%1,%2};" : "=l"(r) : "f"(x), "f"(y)); return r;
}
__device__ __forceinline__ ull fma2(ull a, ull b, ull c) {
    ull d; asm("fma.rn.f32x2 %0, %1, %2, %3;" : "=l"(d) : "l"(a), "l"(b), "l"(c)); return d;
}
__device__ __forceinline__ void unpack2(ull p, float& x, float& y) {
    asm("mov.b64 {%0,%1}, %2;" : "=f"(x), "=f"(y) : "l"(p));
}

// ---------------- software grid barrier ----------------
__device__ __forceinline__ void gridbar() {
    __syncthreads();
    __threadfence();
    if (threadIdx.x == 0) {
        unsigned gen = *(volatile unsigned*)&g_bargen;
        if (atomicAdd(&g_barcnt, 1u) == (unsigned)(CSR_BLOCKS - 1)) {
            g_barcnt = 0;
            __threadfence();
            atomicAdd(&g_bargen, 1u);
        } else {
            while (*(volatile unsigned*)&g_bargen == gen) { }
        }
    }
    __syncthreads();
}

// ---------------- fused CSR build: zero -> count -> scan -> prefix-add -> fill ----------------
__global__ __launch_bounds__(256, 4) void csr_kernel(const int* __restrict__ ei, int E, int n) {
    const int tid = threadIdx.x;
    const int gt = blockIdx.x * 256 + tid;
    const int gstride = CSR_BLOCKS * 256;
    const int tot = E + n;
    const int nbt = (n + 255) / 256;       // 196 scan tiles

    for (int i = gt; i < n; i += gstride) g_deg[i] = 0;
    gridbar();

    for (int e = gt; e < tot; e += gstride) {
        int dst = (e < E) ? ei[E + e] : (e - E);
        atomicAdd(&g_deg[dst], 1);
    }
    gridbar();

    if ((int)blockIdx.x < nbt) {
        __shared__ int wsum[8];
        __shared__ int wpre[8];
        int i = blockIdx.x * 256 + tid;
        int lane = tid & 31, wid = tid >> 5;
        int v = (i < n) ? __ldcg(&g_deg[i]) : 0;
        int incl = v;
        #pragma unroll
        for (int off = 1; off < 32; off <<= 1) {
            int t = __shfl_up_sync(0xffffffffu, incl, off);
            if (lane >= off) incl += t;
        }
        if (lane == 31) wsum[wid] = incl;
        __syncthreads();
        if (tid == 0) {
            int run = 0;
            #pragma unroll
            for (int w = 0; w < 8; w++) { wpre[w] = run; run += wsum[w]; }
            g_bsum[blockIdx.x] = run;
        }
        __syncthreads();
        if (i < n) g_off[i] = wpre[wid] + incl - v;
    }
    gridbar();

    if ((int)blockIdx.x < nbt) {
        __shared__ int spre;
        if (tid < 32) {
            int pre = 0, totdeg = 0;
            for (int i = tid; i < nbt; i += 32) {
                int v = __ldcg(&g_bsum[i]);
                totdeg += v;
                if (i < (int)blockIdx.x) pre += v;
            }
            #pragma unroll
            for (int o = 16; o; o >>= 1) {
                pre    += __shfl_xor_sync(0xffffffffu, pre, o);
                totdeg += __shfl_xor_sync(0xffffffffu, totdeg, o);
            }
            if (tid == 0) {
                spre = pre;
                if (blockIdx.x == 0) g_off[n] = totdeg;
            }
        }
        __syncthreads();
        int i = blockIdx.x * 256 + tid;
        if (i < n) {
            int v = g_off[i] + spre;
            g_off[i] = v;
            g_cur[i] = v;
        }
    }
    gridbar();

    for (int e = gt; e < tot; e += gstride) {
        int src, dst;
        if (e < E) { src = ei[e]; dst = ei[E + e]; }
        else       { src = e - E; dst = src; }
        int p = atomicAdd(&g_cur[dst], 1);
        g_ssrc[p] = src;
    }
}

// ---------------- tiled GEMM: 128x64 block tile, KTILE=64, 8x4 micro-tile ----------------
// Xs k-major [64][128] with XOR-16 column swizzle: store col = r ^ ((k>>5)<<4).
// Per k-step: 2 LDS.128 (x, broadcast) + 1 LDS.128 (w) -> 16 FFMA2.
template <int CIN>
__global__ __launch_bounds__(256, 2) void gemm_alpha_kernel(
        const float* __restrict__ Xin, const float* __restrict__ W,
        const float* __restrict__ avs, const float* __restrict__ avd, int n) {
    __shared__ float Xs[64][128];   // [k][m], swizzled, 32KB
    __shared__ float Ws[64][64];    // [k][c], 16KB
    const float* X = Xin ? Xin : g_o;

    int tid = threadIdx.x;
    int tx = tid & 15;              // 4 cols: tx*4 .. tx*4+3
    int ty = tid >> 4;              // 8 rows: ty*8 .. ty*8+7
    int m0 = blockIdx.x * 128;

    ull acc[8][2];
    #pragma unroll
    for (int r = 0; r < 8; r++) { acc[r][0] = pack2(0.f, 0.f); acc[r][1] = pack2(0.f, 0.f); }

    for (int k0 = 0; k0 < CIN; k0 += 64) {
        // stage X tile transposed+swizzled: thread r=tid>>1 (0..127), kq=(tid&1)*32
        {
            int r = tid >> 1;
            int g = tid & 1;            // k-half -> swizzle group
            int kq = g * 32;
            int row = min(m0 + r, n - 1);
            int colp = r ^ (g << 4);
            const float4* xp = (const float4*)(X + (size_t)row * CIN + k0 + kq);
            #pragma unroll
            for (int i = 0; i < 8; i++) {
                float4 v = xp[i];
                Xs[kq + i * 4 + 0][colp] = v.x;
                Xs[kq + i * 4 + 1][colp] = v.y;
                Xs[kq + i * 4 + 2][colp] = v.z;
                Xs[kq + i * 4 + 3][colp] = v.w;
            }
        }
        // stage W tile [64][64]: thread k=tid>>2, c=(tid&3)*16
        {
            int kk = tid >> 2, c = (tid & 3) * 16;
            const float4* wp = (const float4*)(W + (size_t)(k0 + kk) * CH + c);
            #pragma unroll
            for (int i = 0; i < 4; i++)
                *(float4*)&Ws[kk][c + i * 4] = wp[i];
        }
        __syncthreads();

        #pragma unroll
        for (int kk = 0; kk < 64; kk++) {
            int c0 = (ty * 8) ^ ((kk >> 5) << 4);      // swizzled x base (8-aligned)
            float4 xa = *(const float4*)&Xs[kk][c0];       // rows ty*8+0..3
            float4 xb = *(const float4*)&Xs[kk][c0 + 4];   // rows ty*8+4..7
            float4 wv = *(const float4*)&Ws[kk][tx * 4];
            ull wp0 = pack2(wv.x, wv.y);
            ull wp1 = pack2(wv.z, wv.w);
            ull x0 = pack2(xa.x, xa.x);
            ull x1 = pack2(xa.y, xa.y);
            ull x2 = pack2(xa.z, xa.z);
            ull x3 = pack2(xa.w, xa.w);
            ull x4 = pack2(xb.x, xb.x);
            ull x5 = pack2(xb.y, xb.y);
            ull x6 = pack2(xb.z, xb.z);
            ull x7 = pack2(xb.w, xb.w);
            acc[0][0] = fma2(x0, wp0, acc[0][0]); acc[0][1] = fma2(x0, wp1, acc[0][1]);
            acc[1][0] = fma2(x1, wp0, acc[1][0]); acc[1][1] = fma2(x1, wp1, acc[1][1]);
            acc[2][0] = fma2(x2, wp0, acc[2][0]); acc[2][1] = fma2(x2, wp1, acc[2][1]);
            acc[3][0] = fma2(x3, wp0, acc[3][0]); acc[3][1] = fma2(x3, wp1, acc[3][1]);
            acc[4][0] = fma2(x4, wp0, acc[4][0]); acc[4][1] = fma2(x4, wp1, acc[4][1]);
            acc[5][0] = fma2(x5, wp0, acc[5][0]); acc[5][1] = fma2(x5, wp1, acc[5][1]);
            acc[6][0] = fma2(x6, wp0, acc[6][0]); acc[6][1] = fma2(x6, wp1, acc[6][1]);
            acc[7][0] = fma2(x7, wp0, acc[7][0]); acc[7][1] = fma2(x7, wp1, acc[7][1]);
        }
        __syncthreads();
    }

    float4 av = *(const float4*)&avs[tx * 4];
    float4 dv = *(const float4*)&avd[tx * 4];

    #pragma unroll
    for (int r = 0; r < 8; r++) {
        float c0, c1, c2, c3;
        unpack2(acc[r][0], c0, c1);
        unpack2(acc[r][1], c2, c3);
        int row = m0 + ty * 8 + r;
        float ps = c0 * av.x + c1 * av.y + c2 * av.z + c3 * av.w;
        float pd = c0 * dv.x + c1 * dv.y + c2 * dv.z + c3 * dv.w;
        #pragma unroll
        for (int o = 8; o; o >>= 1) {
            ps += __shfl_xor_sync(0xffffffffu, ps, o, 16);
            pd += __shfl_xor_sync(0xffffffffu, pd, o, 16);
        }
        if (row < n) {
            __half2 p0 = __floats2half2_rn(c0, c1);
            __half2 p1 = __floats2half2_rn(c2, c3);
            union { __half2 h[2]; uint2 u; } pk;
            pk.h[0] = p0; pk.h[1] = p1;
            *(uint2*)((char*)g_h + ((size_t)row << 7) + (tx << 3)) = pk.u;
            if (tx == 0) { g_as[row] = ps; g_ad[row] = pd; }
        }
    }
}

// ---------------- segment softmax + weighted aggregation (fp16 gather) ----------------
__global__ void agg_kernel(const float* __restrict__ bias,
                           float* __restrict__ dout, int n, int mode) {
    int lane = threadIdx.x & 31;
    int qid = lane >> 3;          // quarter 0..3
    int q = lane & 7;             // lane within quarter -> channels q*8..q*8+7
    int gw = (blockIdx.x * blockDim.x + threadIdx.x) >> 5;
    int nw = (gridDim.x * blockDim.x) >> 5;
    float* out = mode ? dout : g_o;

    for (int d = gw; d < n; d += nw) {
        int beg = g_off[d], end = g_off[d + 1];
        float adv = g_ad[d];

        float acc[8];
        #pragma unroll
        for (int i = 0; i < 8; i++) acc[i] = 0.f;
        float denp = 0.f;

        for (int base = beg; base < end; base += 32) {
            int j = base + lane;
            int s = 0;
            float w = 0.f;
            if (j < end) {
                s = g_ssrc[j];
                float e = g_as[s] + adv;
                e = e > 0.f ? e : 0.2f * e;
                w = __expf(e);
            }
            denp += w;
            int cnt = min(32, end - base);
            #pragma unroll 4
            for (int k = 0; k < cnt; k += 4) {
                int e = k + qid;
                int   sk = __shfl_sync(0xffffffffu, s, e & 31);
                float wk = __shfl_sync(0xffffffffu, w, e & 31);
                if (e >= cnt) wk = 0.f;
                uint4 u = *(const uint4*)((const char*)g_h + ((size_t)sk << 7) + (q << 4));
                float2 f0 = __half22float2(*(__half2*)&u.x);
                float2 f1 = __half22float2(*(__half2*)&u.y);
                float2 f2 = __half22float2(*(__half2*)&u.z);
                float2 f3 = __half22float2(*(__half2*)&u.w);
                acc[0] = fmaf(wk, f0.x, acc[0]);
                acc[1] = fmaf(wk, f0.y, acc[1]);
                acc[2] = fmaf(wk, f1.x, acc[2]);
                acc[3] = fmaf(wk, f1.y, acc[3]);
                acc[4] = fmaf(wk, f2.x, acc[4]);
                acc[5] = fmaf(wk, f2.y, acc[5]);
                acc[6] = fmaf(wk, f3.x, acc[6]);
                acc[7] = fmaf(wk, f3.y, acc[7]);
            }
        }
        #pragma unroll
        for (int i = 0; i < 8; i++) {
            acc[i] += __shfl_xor_sync(0xffffffffu, acc[i], 8);
            acc[i] += __shfl_xor_sync(0xffffffffu, acc[i], 16);
        }
        float den = denp;
        #pragma unroll
        for (int o = 16; o; o >>= 1) den += __shfl_xor_sync(0xffffffffu, den, o);

        if (qid == 0) {
            float inv = 1.f / den;
            const float4* b4 = (const float4*)bias;
            float4 bv0 = b4[q * 2], bv1 = b4[q * 2 + 1];
            float4 o0, o1;
            o0.x = acc[0] * inv + bv0.x;
            o0.y = acc[1] * inv + bv0.y;
            o0.z = acc[2] * inv + bv0.z;
            o0.w = acc[3] * inv + bv0.w;
            o1.x = acc[4] * inv + bv1.x;
            o1.y = acc[5] * inv + bv1.y;
            o1.z = acc[6] * inv + bv1.z;
            o1.w = acc[7] * inv + bv1.w;
            if (mode == 0) {  // ELU for layers 1 & 2
                o0.x = o0.x > 0.f ? o0.x : (__expf(o0.x) - 1.f);
                o0.y = o0.y > 0.f ? o0.y : (__expf(o0.y) - 1.f);
                o0.z = o0.z > 0.f ? o0.z : (__expf(o0.z) - 1.f);
                o0.w = o0.w > 0.f ? o0.w : (__expf(o0.w) - 1.f);
                o1.x = o1.x > 0.f ? o1.x : (__expf(o1.x) - 1.f);
                o1.y = o1.y > 0.f ? o1.y : (__expf(o1.y) - 1.f);
                o1.z = o1.z > 0.f ? o1.z : (__expf(o1.z) - 1.f);
                o1.w = o1.w > 0.f ? o1.w : (__expf(o1.w) - 1.f);
            }
            float4* orow = (float4*)(out + (size_t)d * CH);
            orow[q * 2]     = o0;
            orow[q * 2 + 1] = o1;
        }
    }
}

// ---------------- launch ----------------
extern "C" void kernel_launch(void* const* d_in, const int* in_sizes, int n_in,
                              void* d_out, int out_size) {
    const float* x     = (const float*)d_in[0];
    const int*   ei    = (const int*)d_in[1];
    const float* W1    = (const float*)d_in[2];
    const float* asr1  = (const float*)d_in[3];
    const float* adt1  = (const float*)d_in[4];
    const float* b1    = (const float*)d_in[5];
    const float* W2    = (const float*)d_in[6];
    const float* asr2  = (const float*)d_in[7];
    const float* adt2  = (const float*)d_in[8];
    const float* b2    = (const float*)d_in[9];
    const float* W3    = (const float*)d_in[10];
    const float* asr3  = (const float*)d_in[11];
    const float* adt3  = (const float*)d_in[12];
    const float* b3    = (const float*)d_in[13];

    int n = in_sizes[0] / 128;   // 50000
    int E = in_sizes[1] / 2;     // 800000
    float* dout = (float*)d_out;

    csr_kernel<<<CSR_BLOCKS, 256>>>(ei, E, n);

    int aggGrid = (n * 32 + 255) / 256;
    int gemmGrid = (n + 127) / 128;

    gemm_alpha_kernel<128><<<gemmGrid, 256>>>(x, W1, asr1, adt1, n);
    agg_kernel<<<aggGrid, 256>>>(b1, dout, n, 0);

    gemm_alpha_kernel<64><<<gemmGrid, 256>>>(nullptr, W2, asr2, adt2, n);
    agg_kernel<<<aggGrid, 256>>>(b2, dout, n, 0);

    gemm_alpha_kernel<64><<<gemmGrid, 256>>>(nullptr, W3, asr3, adt3, n);
    agg_kernel<<<aggGrid, 256>>>(b3, dout, n, 1);
}

// round 11
// speedup vs baseline: 3.2519x; 1.1474x over previous
#include <cuda_runtime.h>
#include <cuda_fp16.h>

#define NN 50000
#define EE 800000
#define ET (EE + NN)
#define CH 64
#define CSR_BLOCKS 592   // 148 SMs x 4 blocks co-resident

// ---------------- scratch (static device globals; no allocation) ----------------
__device__ __align__(256) __half g_h[(size_t)NN * CH];  // h = X @ W, fp16 (row = 128B)
__device__ __align__(256) float  g_o[(size_t)NN * CH];  // aggregated output (fp32)
__device__ float g_as[NN];
__device__ float g_ad[NN];
__device__ int   g_deg[NN];
__device__ int   g_cur[NN];
__device__ int   g_off[NN + 1];
__device__ int   g_bsum[256];
__device__ int   g_ssrc[ET];
__device__ unsigned g_barcnt;
__device__ unsigned g_bargen;

// ---------------- software grid barrier ----------------
__device__ __forceinline__ void gridbar() {
    __syncthreads();
    __threadfence();
    if (threadIdx.x == 0) {
        unsigned gen = *(volatile unsigned*)&g_bargen;
        if (atomicAdd(&g_barcnt, 1u) == (unsigned)(CSR_BLOCKS - 1)) {
            g_barcnt = 0;
            __threadfence();
            atomicAdd(&g_bargen, 1u);
        } else {
            while (*(volatile unsigned*)&g_bargen == gen) { }
        }
    }
    __syncthreads();
}

// ---------------- fused CSR build ----------------
__global__ __launch_bounds__(256, 4) void csr_kernel(const int* __restrict__ ei, int E, int n) {
    const int tid = threadIdx.x;
    const int gt = blockIdx.x * 256 + tid;
    const int gstride = CSR_BLOCKS * 256;
    const int tot = E + n;
    const int nbt = (n + 255) / 256;

    for (int i = gt; i < n; i += gstride) g_deg[i] = 0;
    gridbar();

    for (int e = gt; e < tot; e += gstride) {
        int dst = (e < E) ? ei[E + e] : (e - E);
        atomicAdd(&g_deg[dst], 1);
    }
    gridbar();

    if ((int)blockIdx.x < nbt) {
        __shared__ int wsum[8];
        __shared__ int wpre[8];
        int i = blockIdx.x * 256 + tid;
        int lane = tid & 31, wid = tid >> 5;
        int v = (i < n) ? __ldcg(&g_deg[i]) : 0;
        int incl = v;
        #pragma unroll
        for (int off = 1; off < 32; off <<= 1) {
            int t = __shfl_up_sync(0xffffffffu, incl, off);
            if (lane >= off) incl += t;
        }
        if (lane == 31) wsum[wid] = incl;
        __syncthreads();
        if (tid == 0) {
            int run = 0;
            #pragma unroll
            for (int w = 0; w < 8; w++) { wpre[w] = run; run += wsum[w]; }
            g_bsum[blockIdx.x] = run;
        }
        __syncthreads();
        if (i < n) g_off[i] = wpre[wid] + incl - v;
    }
    gridbar();

    if ((int)blockIdx.x < nbt) {
        __shared__ int spre;
        if (tid < 32) {
            int pre = 0, totdeg = 0;
            for (int i = tid; i < nbt; i += 32) {
                int v = __ldcg(&g_bsum[i]);
                totdeg += v;
                if (i < (int)blockIdx.x) pre += v;
            }
            #pragma unroll
            for (int o = 16; o; o >>= 1) {
                pre    += __shfl_xor_sync(0xffffffffu, pre, o);
                totdeg += __shfl_xor_sync(0xffffffffu, totdeg, o);
            }
            if (tid == 0) {
                spre = pre;
                if (blockIdx.x == 0) g_off[n] = totdeg;
            }
        }
        __syncthreads();
        int i = blockIdx.x * 256 + tid;
        if (i < n) {
            int v = g_off[i] + spre;
            g_off[i] = v;
            g_cur[i] = v;
        }
    }
    gridbar();

    for (int e = gt; e < tot; e += gstride) {
        int src, dst;
        if (e < E) { src = ei[e]; dst = ei[E + e]; }
        else       { src = e - E; dst = src; }
        int p = atomicAdd(&g_cur[dst], 1);
        g_ssrc[p] = src;
    }
}

// ---------------- tensor-core GEMM (HMMA m16n8k16) + fused alpha ----------------
// Block: 128 rows x 64 cols, K fully staged. 8 warps, warp w -> rows w*16..w*16+15.
// Xs: fp16 [128][CIN], 16B units swizzled u' = u ^ (row&7)  -> conflict-free ldmatrix.
// Wt: fp16 [64][CIN] (W transposed), units swizzled u' = u ^ (n&7) -> LDS.32 B frags.
template <int CIN>
__global__ __launch_bounds__(256, 2) void gemm_alpha_kernel(
        const float* __restrict__ Xin, const float* __restrict__ W,
        const float* __restrict__ avs, const float* __restrict__ avd, int n) {
    constexpr int CU = CIN / 8;          // 16B units per row
    __shared__ __half Xs[128 * CIN];     // 32KB (CIN=128) / 16KB
    __shared__ __half Wt[64 * CIN];      // 16KB / 8KB

    const float* X = Xin ? Xin : g_o;
    int tid = threadIdx.x;
    int lane = tid & 31;
    int wid = tid >> 5;
    int m0 = blockIdx.x * 128;

    // ---- stage X: fp32 -> fp16, one 16B unit at a time, swizzled ----
    {
        int row = tid >> 1;
        int row_c = min(m0 + row, n - 1);
        const float4* xp = (const float4*)(X + (size_t)row_c * CIN);
        #pragma unroll
        for (int i = 0; i < CU / 2; i++) {
            int u = (tid & 1) * (CU / 2) + i;
            float4 v0 = xp[u * 2];
            float4 v1 = xp[u * 2 + 1];
            union { __half2 h[4]; uint4 q; } pk;
            pk.h[0] = __floats2half2_rn(v0.x, v0.y);
            pk.h[1] = __floats2half2_rn(v0.z, v0.w);
            pk.h[2] = __floats2half2_rn(v1.x, v1.y);
            pk.h[3] = __floats2half2_rn(v1.z, v1.w);
            int up = u ^ (row & 7);
            *(uint4*)&Xs[(row * CU + up) * 8] = pk.q;
        }
    }
    // ---- stage W transposed: Wt[n][k] fp16, swizzled ----
    {
        int nn = tid & 63;
        int ub = tid >> 6;                 // 0..3
        #pragma unroll
        for (int i = 0; i < CU / 4; i++) {
            int u = ub + i * 4;
            union { __half2 h[4]; uint4 q; } pk;
            #pragma unroll
            for (int j = 0; j < 4; j++) {
                float w0 = W[(size_t)(u * 8 + j * 2) * CH + nn];
                float w1 = W[(size_t)(u * 8 + j * 2 + 1) * CH + nn];
                pk.h[j] = __floats2half2_rn(w0, w1);
            }
            int up = u ^ (nn & 7);
            *(uint4*)&Wt[(nn * CU + up) * 8] = pk.q;
        }
    }
    __syncthreads();

    // smem u32 bases
    unsigned xsb, wtb;
    {
        unsigned long long t;
        asm("cvta.to.shared.u64 %0, %1;" : "=l"(t) : "l"(Xs)); xsb = (unsigned)t;
        asm("cvta.to.shared.u64 %0, %1;" : "=l"(t) : "l"(Wt)); wtb = (unsigned)t;
    }

    float c[8][4];
    #pragma unroll
    for (int t = 0; t < 8; t++) { c[t][0] = c[t][1] = c[t][2] = c[t][3] = 0.f; }

    int arow = lane & 15;                    // row within warp strip
    int aub = lane >> 4;                     // k-unit sub-block
    int bg = lane >> 2;                      // n within 8-row group
    int bw = lane & 3;                       // word within B unit

    #pragma unroll
    for (int ks = 0; ks < CIN / 16; ks++) {
        unsigned a0, a1, a2, a3;
        int au = (ks * 2 + aub) ^ (arow & 7);
        unsigned aaddr = xsb + ((wid * 16 + arow) * CU + au) * 16;
        asm volatile("ldmatrix.sync.aligned.m8n8.x4.shared.b16 {%0,%1,%2,%3}, [%4];"
                     : "=r"(a0), "=r"(a1), "=r"(a2), "=r"(a3) : "r"(aaddr));
        #pragma unroll
        for (int t = 0; t < 8; t++) {
            int nrow = t * 8 + bg;
            unsigned b0 = *(const unsigned*)((const char*)Wt +
                          ((nrow * CU + ((ks * 2) ^ bg)) * 16 + bw * 4));
            unsigned b1 = *(const unsigned*)((const char*)Wt +
                          ((nrow * CU + ((ks * 2 + 1) ^ bg)) * 16 + bw * 4));
            asm volatile("mma.sync.aligned.m16n8k16.row.col.f32.f16.f16.f32 "
                         "{%0,%1,%2,%3}, {%4,%5,%6,%7}, {%8,%9}, {%0,%1,%2,%3};"
                         : "+f"(c[t][0]), "+f"(c[t][1]), "+f"(c[t][2]), "+f"(c[t][3])
                         : "r"(a0), "r"(a1), "r"(a2), "r"(a3), "r"(b0), "r"(b1));
        }
    }

    // ---- epilogue: alpha dots from fragments + fp16 h store ----
    int r0 = m0 + wid * 16 + (lane >> 2);
    int r1 = r0 + 8;
    float psA = 0.f, pdA = 0.f, psB = 0.f, pdB = 0.f;
    #pragma unroll
    for (int t = 0; t < 8; t++) {
        int col = t * 8 + (lane & 3) * 2;
        float as0 = avs[col], as1 = avs[col + 1];
        float ad0 = avd[col], ad1 = avd[col + 1];
        psA += c[t][0] * as0 + c[t][1] * as1;
        pdA += c[t][0] * ad0 + c[t][1] * ad1;
        psB += c[t][2] * as0 + c[t][3] * as1;
        pdB += c[t][2] * ad0 + c[t][3] * ad1;
        if (r0 < n)
            *(__half2*)((char*)g_h + ((size_t)r0 << 7) + col * 2) = __floats2half2_rn(c[t][0], c[t][1]);
        if (r1 < n)
            *(__half2*)((char*)g_h + ((size_t)r1 << 7) + col * 2) = __floats2half2_rn(c[t][2], c[t][3]);
    }
    #pragma unroll
    for (int o = 1; o <= 2; o <<= 1) {
        psA += __shfl_xor_sync(0xffffffffu, psA, o);
        pdA += __shfl_xor_sync(0xffffffffu, pdA, o);
        psB += __shfl_xor_sync(0xffffffffu, psB, o);
        pdB += __shfl_xor_sync(0xffffffffu, pdB, o);
    }
    if ((lane & 3) == 0) {
        if (r0 < n) { g_as[r0] = psA; g_ad[r0] = pdA; }
        if (r1 < n) { g_as[r1] = psB; g_ad[r1] = pdB; }
    }
}

// ---------------- segment softmax + weighted aggregation (fp16 gather) ----------------
__global__ void agg_kernel(const float* __restrict__ bias,
                           float* __restrict__ dout, int n, int mode) {
    int lane = threadIdx.x & 31;
    int qid = lane >> 3;
    int q = lane & 7;
    int gw = (blockIdx.x * blockDim.x + threadIdx.x) >> 5;
    int nw = (gridDim.x * blockDim.x) >> 5;
    float* out = mode ? dout : g_o;

    for (int d = gw; d < n; d += nw) {
        int beg = g_off[d], end = g_off[d + 1];
        float adv = g_ad[d];

        float acc[8];
        #pragma unroll
        for (int i = 0; i < 8; i++) acc[i] = 0.f;
        float denp = 0.f;

        for (int base = beg; base < end; base += 32) {
            int j = base + lane;
            int s = 0;
            float w = 0.f;
            if (j < end) {
                s = g_ssrc[j];
                float e = g_as[s] + adv;
                e = e > 0.f ? e : 0.2f * e;
                w = __expf(e);
            }
            denp += w;
            int cnt = min(32, end - base);
            #pragma unroll 4
            for (int k = 0; k < cnt; k += 4) {
                int e = k + qid;
                int   sk = __shfl_sync(0xffffffffu, s, e & 31);
                float wk = __shfl_sync(0xffffffffu, w, e & 31);
                if (e >= cnt) wk = 0.f;
                uint4 u = *(const uint4*)((const char*)g_h + ((size_t)sk << 7) + (q << 4));
                float2 f0 = __half22float2(*(__half2*)&u.x);
                float2 f1 = __half22float2(*(__half2*)&u.y);
                float2 f2 = __half22float2(*(__half2*)&u.z);
                float2 f3 = __half22float2(*(__half2*)&u.w);
                acc[0] = fmaf(wk, f0.x, acc[0]);
                acc[1] = fmaf(wk, f0.y, acc[1]);
                acc[2] = fmaf(wk, f1.x, acc[2]);
                acc[3] = fmaf(wk, f1.y, acc[3]);
                acc[4] = fmaf(wk, f2.x, acc[4]);
                acc[5] = fmaf(wk, f2.y, acc[5]);
                acc[6] = fmaf(wk, f3.x, acc[6]);
                acc[7] = fmaf(wk, f3.y, acc[7]);
            }
        }
        #pragma unroll
        for (int i = 0; i < 8; i++) {
            acc[i] += __shfl_xor_sync(0xffffffffu, acc[i], 8);
            acc[i] += __shfl_xor_sync(0xffffffffu, acc[i], 16);
        }
        float den = denp;
        #pragma unroll
        for (int o = 16; o; o >>= 1) den += __shfl_xor_sync(0xffffffffu, den, o);

        if (qid == 0) {
            float inv = 1.f / den;
            const float4* b4 = (const float4*)bias;
            float4 bv0 = b4[q * 2], bv1 = b4[q * 2 + 1];
            float4 o0, o1;
            o0.x = acc[0] * inv + bv0.x;
            o0.y = acc[1] * inv + bv0.y;
            o0.z = acc[2] * inv + bv0.z;
            o0.w = acc[3] * inv + bv0.w;
            o1.x = acc[4] * inv + bv1.x;
            o1.y = acc[5] * inv + bv1.y;
            o1.z = acc[6] * inv + bv1.z;
            o1.w = acc[7] * inv + bv1.w;
            if (mode == 0) {
                o0.x = o0.x > 0.f ? o0.x : (__expf(o0.x) - 1.f);
                o0.y = o0.y > 0.f ? o0.y : (__expf(o0.y) - 1.f);
                o0.z = o0.z > 0.f ? o0.z : (__expf(o0.z) - 1.f);
                o0.w = o0.w > 0.f ? o0.w : (__expf(o0.w) - 1.f);
                o1.x = o1.x > 0.f ? o1.x : (__expf(o1.x) - 1.f);
                o1.y = o1.y > 0.f ? o1.y : (__expf(o1.y) - 1.f);
                o1.z = o1.z > 0.f ? o1.z : (__expf(o1.z) - 1.f);
                o1.w = o1.w > 0.f ? o1.w : (__expf(o1.w) - 1.f);
            }
            float4* orow = (float4*)(out + (size_t)d * CH);
            orow[q * 2]     = o0;
            orow[q * 2 + 1] = o1;
        }
    }
}

// ---------------- launch ----------------
extern "C" void kernel_launch(void* const* d_in, const int* in_sizes, int n_in,
                              void* d_out, int out_size) {
    const float* x     = (const float*)d_in[0];
    const int*   ei    = (const int*)d_in[1];
    const float* W1    = (const float*)d_in[2];
    const float* asr1  = (const float*)d_in[3];
    const float* adt1  = (const float*)d_in[4];
    const float* b1    = (const float*)d_in[5];
    const float* W2    = (const float*)d_in[6];
    const float* asr2  = (const float*)d_in[7];
    const float* adt2  = (const float*)d_in[8];
    const float* b2    = (const float*)d_in[9];
    const float* W3    = (const float*)d_in[10];
    const float* asr3  = (const float*)d_in[11];
    const float* adt3  = (const float*)d_in[12];
    const float* b3    = (const float*)d_in[13];

    int n = in_sizes[0] / 128;   // 50000
    int E = in_sizes[1] / 2;     // 800000
    float* dout = (float*)d_out;

    csr_kernel<<<CSR_BLOCKS, 256>>>(ei, E, n);

    int aggGrid = (n * 32 + 255) / 256;
    int gemmGrid = (n + 127) / 128;

    gemm_alpha_kernel<128><<<gemmGrid, 256>>>(x, W1, asr1, adt1, n);
    agg_kernel<<<aggGrid, 256>>>(b1, dout, n, 0);

    gemm_alpha_kernel<64><<<gemmGrid, 256>>>(nullptr, W2, asr2, adt2, n);
    agg_kernel<<<aggGrid, 256>>>(b2, dout, n, 0);

    gemm_alpha_kernel<64><<<gemmGrid, 256>>>(nullptr, W3, asr3, adt3, n);
    agg_kernel<<<aggGrid, 256>>>(b3, dout, n, 1);
}

// round 12
// speedup vs baseline: 3.4892x; 1.0730x over previous
#include <cuda_runtime.h>
#include <cuda_fp16.h>

#define NN 50000
#define EE 800000
#define ET (EE + NN)
#define CH 64
#define CSR_BLOCKS 592   // 148 SMs x 4 blocks co-resident

// ---------------- scratch (static device globals; no allocation) ----------------
__device__ __align__(256) __half g_h[(size_t)NN * CH];    // gemm out fp16 (row=128B)
__device__ __align__(256) float  g_o[(size_t)NN * CH];    // agg out fp32 (for rel-err path)
__device__ __align__(256) __half g_oh[(size_t)NN * CH];   // agg out fp16, pre-swizzled
__device__ __align__(256) __half g_xh[(size_t)NN * 128];  // layer-1 input fp16, pre-swizzled
__device__ __align__(256) __half g_wt1[64 * 128];         // W1^T fp16 pre-swizzled
__device__ __align__(256) __half g_wt2[64 * 64];
__device__ __align__(256) __half g_wt3[64 * 64];
__device__ float g_as[NN];
__device__ float g_ad[NN];
__device__ int   g_deg[NN];
__device__ int   g_cur[NN];
__device__ int   g_off[NN + 1];
__device__ int   g_bsum[256];
__device__ int   g_ssrc[ET];
__device__ unsigned g_barcnt;
__device__ unsigned g_bargen;

// ---------------- software grid barrier ----------------
__device__ __forceinline__ void gridbar() {
    __syncthreads();
    __threadfence();
    if (threadIdx.x == 0) {
        unsigned gen = *(volatile unsigned*)&g_bargen;
        if (atomicAdd(&g_barcnt, 1u) == (unsigned)(CSR_BLOCKS - 1)) {
            g_barcnt = 0;
            __threadfence();
            atomicAdd(&g_bargen, 1u);
        } else {
            while (*(volatile unsigned*)&g_bargen == gen) { }
        }
    }
    __syncthreads();
}

// ---------------- fused CSR build + fp16 precompute ----------------
__global__ __launch_bounds__(256, 4) void csr_kernel(
        const int* __restrict__ ei, const float* __restrict__ x,
        const float* __restrict__ W1, const float* __restrict__ W2,
        const float* __restrict__ W3, int E, int n) {
    const int tid = threadIdx.x;
    const int gt = blockIdx.x * 256 + tid;
    const int gstride = CSR_BLOCKS * 256;
    const int tot = E + n;
    const int nbt = (n + 255) / 256;

    // phase 0a: zero degree counters
    for (int i = gt; i < n; i += gstride) g_deg[i] = 0;

    // phase 0b: convert x -> g_xh (fp16, pre-swizzled u^(row&7)), CU=16
    for (int idx = gt; idx < n * 16; idx += gstride) {
        int row = idx >> 4, u = idx & 15;
        const float4* xp = (const float4*)(x + (size_t)row * 128 + u * 8);
        float4 v0 = xp[0], v1 = xp[1];
        union { __half2 h[4]; uint4 q; } pk;
        pk.h[0] = __floats2half2_rn(v0.x, v0.y);
        pk.h[1] = __floats2half2_rn(v0.z, v0.w);
        pk.h[2] = __floats2half2_rn(v1.x, v1.y);
        pk.h[3] = __floats2half2_rn(v1.z, v1.w);
        *(uint4*)&g_xh[((size_t)row * 16 + (u ^ (row & 7))) * 8] = pk.q;
    }
    // phase 0c: transpose+convert weights (pre-swizzled u^(nn&7))
    for (int idx = gt; idx < 64 * 16; idx += gstride) {   // W1: CU=16
        int nn = idx >> 4, u = idx & 15;
        union { __half2 h[4]; uint4 q; } pk;
        #pragma unroll
        for (int j = 0; j < 4; j++) {
            float w0 = W1[(size_t)(u * 8 + j * 2) * CH + nn];
            float w1 = W1[(size_t)(u * 8 + j * 2 + 1) * CH + nn];
            pk.h[j] = __floats2half2_rn(w0, w1);
        }
        *(uint4*)&g_wt1[(nn * 16 + (u ^ (nn & 7))) * 8] = pk.q;
    }
    for (int idx = gt; idx < 64 * 8 * 2; idx += gstride) {  // W2+W3: CU=8
        int which = idx >= 64 * 8;
        int id2 = idx - which * 64 * 8;
        int nn = id2 >> 3, u = id2 & 7;
        const float* W = which ? W3 : W2;
        union { __half2 h[4]; uint4 q; } pk;
        #pragma unroll
        for (int j = 0; j < 4; j++) {
            float w0 = W[(size_t)(u * 8 + j * 2) * CH + nn];
            float w1 = W[(size_t)(u * 8 + j * 2 + 1) * CH + nn];
            pk.h[j] = __floats2half2_rn(w0, w1);
        }
        __half* dst = which ? g_wt3 : g_wt2;
        *(uint4*)&dst[(nn * 8 + (u ^ (nn & 7))) * 8] = pk.q;
    }
    gridbar();

    // phase 1: count in-degree
    for (int e = gt; e < tot; e += gstride) {
        int dst = (e < E) ? ei[E + e] : (e - E);
        atomicAdd(&g_deg[dst], 1);
    }
    gridbar();

    // phase 2: per-tile scan
    if ((int)blockIdx.x < nbt) {
        __shared__ int wsum[8];
        __shared__ int wpre[8];
        int i = blockIdx.x * 256 + tid;
        int lane = tid & 31, wid = tid >> 5;
        int v = (i < n) ? __ldcg(&g_deg[i]) : 0;
        int incl = v;
        #pragma unroll
        for (int off = 1; off < 32; off <<= 1) {
            int t = __shfl_up_sync(0xffffffffu, incl, off);
            if (lane >= off) incl += t;
        }
        if (lane == 31) wsum[wid] = incl;
        __syncthreads();
        if (tid == 0) {
            int run = 0;
            #pragma unroll
            for (int w = 0; w < 8; w++) { wpre[w] = run; run += wsum[w]; }
            g_bsum[blockIdx.x] = run;
        }
        __syncthreads();
        if (i < n) g_off[i] = wpre[wid] + incl - v;
    }
    gridbar();

    // phase 3: prefix-add + cursors
    if ((int)blockIdx.x < nbt) {
        __shared__ int spre;
        if (tid < 32) {
            int pre = 0, totdeg = 0;
            for (int i = tid; i < nbt; i += 32) {
                int v = __ldcg(&g_bsum[i]);
                totdeg += v;
                if (i < (int)blockIdx.x) pre += v;
            }
            #pragma unroll
            for (int o = 16; o; o >>= 1) {
                pre    += __shfl_xor_sync(0xffffffffu, pre, o);
                totdeg += __shfl_xor_sync(0xffffffffu, totdeg, o);
            }
            if (tid == 0) {
                spre = pre;
                if (blockIdx.x == 0) g_off[n] = totdeg;
            }
        }
        __syncthreads();
        int i = blockIdx.x * 256 + tid;
        if (i < n) {
            int v = g_off[i] + spre;
            g_off[i] = v;
            g_cur[i] = v;
        }
    }
    gridbar();

    // phase 4: fill CSR
    for (int e = gt; e < tot; e += gstride) {
        int src, dst;
        if (e < E) { src = ei[e]; dst = ei[E + e]; }
        else       { src = e - E; dst = src; }
        int p = atomicAdd(&g_cur[dst], 1);
        g_ssrc[p] = src;
    }
}

// ---------------- tensor-core GEMM (HMMA m16n8k16) + fused alpha ----------------
// Inputs pre-converted fp16 + pre-swizzled. sel: 0 -> (g_xh, g_wt1), 1 -> (g_oh, g_wt2),
// 2 -> (g_oh, g_wt3). Staging = contiguous uint4 copy.
template <int CIN>
__global__ __launch_bounds__(256, 3) void gemm_alpha_kernel(
        int sel, const float* __restrict__ avs, const float* __restrict__ avd, int n) {
    constexpr int CU = CIN / 8;
    __shared__ __half Xs[128 * CIN];
    __shared__ __half Ws[64 * CIN];

    const __half* Xh = (sel == 0) ? g_xh : g_oh;
    const __half* Wt = (sel == 0) ? g_wt1 : ((sel == 1) ? g_wt2 : g_wt3);

    int tid = threadIdx.x;
    int lane = tid & 31;
    int wid = tid >> 5;
    int m0 = blockIdx.x * 128;

    // ---- stage X: contiguous copy (pre-swizzled source) ----
    if (m0 + 128 <= n) {
        const uint4* src = (const uint4*)(Xh + (size_t)m0 * CIN);
        uint4* dst = (uint4*)Xs;
        #pragma unroll
        for (int i = 0; i < 128 * CU / 256; i++)
            dst[tid + i * 256] = src[tid + i * 256];
    } else {
        for (int idx = tid; idx < 128 * CU; idx += 256) {
            int row = idx / CU, u = idx - row * CU;
            int rowc = min(m0 + row, n - 1);
            *(uint4*)&Xs[(size_t)idx * 8] = *(const uint4*)&Xh[((size_t)rowc * CU + u) * 8];
        }
    }
    // ---- stage W: contiguous copy ----
    {
        const uint4* src = (const uint4*)Wt;
        uint4* dst = (uint4*)Ws;
        #pragma unroll
        for (int i = 0; i < 64 * CU / 256; i++)
            dst[tid + i * 256] = src[tid + i * 256];
    }
    __syncthreads();

    unsigned xsb;
    {
        unsigned long long t;
        asm("cvta.to.shared.u64 %0, %1;" : "=l"(t) : "l"(Xs)); xsb = (unsigned)t;
    }

    float c[8][4];
    #pragma unroll
    for (int t = 0; t < 8; t++) { c[t][0] = c[t][1] = c[t][2] = c[t][3] = 0.f; }

    int arow = lane & 15;
    int aub = lane >> 4;
    int bg = lane >> 2;
    int bw = lane & 3;

    #pragma unroll
    for (int ks = 0; ks < CIN / 16; ks++) {
        unsigned a0, a1, a2, a3;
        int au = (ks * 2 + aub) ^ (arow & 7);
        unsigned aaddr = xsb + ((wid * 16 + arow) * CU + au) * 16;
        asm volatile("ldmatrix.sync.aligned.m8n8.x4.shared.b16 {%0,%1,%2,%3}, [%4];"
                     : "=r"(a0), "=r"(a1), "=r"(a2), "=r"(a3) : "r"(aaddr));
        #pragma unroll
        for (int t = 0; t < 8; t++) {
            int nrow = t * 8 + bg;
            unsigned b0 = *(const unsigned*)((const char*)Ws +
                          ((nrow * CU + ((ks * 2) ^ bg)) * 16 + bw * 4));
            unsigned b1 = *(const unsigned*)((const char*)Ws +
                          ((nrow * CU + ((ks * 2 + 1) ^ bg)) * 16 + bw * 4));
            asm volatile("mma.sync.aligned.m16n8k16.row.col.f32.f16.f16.f32 "
                         "{%0,%1,%2,%3}, {%4,%5,%6,%7}, {%8,%9}, {%0,%1,%2,%3};"
                         : "+f"(c[t][0]), "+f"(c[t][1]), "+f"(c[t][2]), "+f"(c[t][3])
                         : "r"(a0), "r"(a1), "r"(a2), "r"(a3), "r"(b0), "r"(b1));
        }
    }

    // ---- epilogue: alpha dots from fragments + fp16 h store ----
    int r0 = m0 + wid * 16 + (lane >> 2);
    int r1 = r0 + 8;
    float psA = 0.f, pdA = 0.f, psB = 0.f, pdB = 0.f;
    #pragma unroll
    for (int t = 0; t < 8; t++) {
        int col = t * 8 + (lane & 3) * 2;
        float as0 = avs[col], as1 = avs[col + 1];
        float ad0 = avd[col], ad1 = avd[col + 1];
        psA += c[t][0] * as0 + c[t][1] * as1;
        pdA += c[t][0] * ad0 + c[t][1] * ad1;
        psB += c[t][2] * as0 + c[t][3] * as1;
        pdB += c[t][2] * ad0 + c[t][3] * ad1;
        if (r0 < n)
            *(__half2*)((char*)g_h + ((size_t)r0 << 7) + col * 2) = __floats2half2_rn(c[t][0], c[t][1]);
        if (r1 < n)
            *(__half2*)((char*)g_h + ((size_t)r1 << 7) + col * 2) = __floats2half2_rn(c[t][2], c[t][3]);
    }
    #pragma unroll
    for (int o = 1; o <= 2; o <<= 1) {
        psA += __shfl_xor_sync(0xffffffffu, psA, o);
        pdA += __shfl_xor_sync(0xffffffffu, pdA, o);
        psB += __shfl_xor_sync(0xffffffffu, psB, o);
        pdB += __shfl_xor_sync(0xffffffffu, pdB, o);
    }
    if ((lane & 3) == 0) {
        if (r0 < n) { g_as[r0] = psA; g_ad[r0] = pdA; }
        if (r1 < n) { g_as[r1] = psB; g_ad[r1] = pdB; }
    }
}

// ---------------- segment softmax + weighted aggregation (fp16 gather) ----------------
__global__ void agg_kernel(const float* __restrict__ bias,
                           float* __restrict__ dout, int n, int mode) {
    int lane = threadIdx.x & 31;
    int qid = lane >> 3;
    int q = lane & 7;
    int gw = (blockIdx.x * blockDim.x + threadIdx.x) >> 5;
    int nw = (gridDim.x * blockDim.x) >> 5;
    float* out = mode ? dout : g_o;

    for (int d = gw; d < n; d += nw) {
        int beg = g_off[d], end = g_off[d + 1];
        float adv = g_ad[d];

        float acc[8];
        #pragma unroll
        for (int i = 0; i < 8; i++) acc[i] = 0.f;
        float denp = 0.f;

        for (int base = beg; base < end; base += 32) {
            int j = base + lane;
            int s = 0;
            float w = 0.f;
            if (j < end) {
                s = g_ssrc[j];
                float e = g_as[s] + adv;
                e = e > 0.f ? e : 0.2f * e;
                w = __expf(e);
            }
            denp += w;
            int cnt = min(32, end - base);
            #pragma unroll 4
            for (int k = 0; k < cnt; k += 4) {
                int e = k + qid;
                int   sk = __shfl_sync(0xffffffffu, s, e & 31);
                float wk = __shfl_sync(0xffffffffu, w, e & 31);
                if (e >= cnt) wk = 0.f;
                uint4 u = *(const uint4*)((const char*)g_h + ((size_t)sk << 7) + (q << 4));
                float2 f0 = __half22float2(*(__half2*)&u.x);
                float2 f1 = __half22float2(*(__half2*)&u.y);
                float2 f2 = __half22float2(*(__half2*)&u.z);
                float2 f3 = __half22float2(*(__half2*)&u.w);
                acc[0] = fmaf(wk, f0.x, acc[0]);
                acc[1] = fmaf(wk, f0.y, acc[1]);
                acc[2] = fmaf(wk, f1.x, acc[2]);
                acc[3] = fmaf(wk, f1.y, acc[3]);
                acc[4] = fmaf(wk, f2.x, acc[4]);
                acc[5] = fmaf(wk, f2.y, acc[5]);
                acc[6] = fmaf(wk, f3.x, acc[6]);
                acc[7] = fmaf(wk, f3.y, acc[7]);
            }
        }
        #pragma unroll
        for (int i = 0; i < 8; i++) {
            acc[i] += __shfl_xor_sync(0xffffffffu, acc[i], 8);
            acc[i] += __shfl_xor_sync(0xffffffffu, acc[i], 16);
        }
        float den = denp;
        #pragma unroll
        for (int o = 16; o; o >>= 1) den += __shfl_xor_sync(0xffffffffu, den, o);

        if (qid == 0) {
            float inv = 1.f / den;
            const float4* b4 = (const float4*)bias;
            float4 bv0 = b4[q * 2], bv1 = b4[q * 2 + 1];
            float4 o0, o1;
            o0.x = acc[0] * inv + bv0.x;
            o0.y = acc[1] * inv + bv0.y;
            o0.z = acc[2] * inv + bv0.z;
            o0.w = acc[3] * inv + bv0.w;
            o1.x = acc[4] * inv + bv1.x;
            o1.y = acc[5] * inv + bv1.y;
            o1.z = acc[6] * inv + bv1.z;
            o1.w = acc[7] * inv + bv1.w;
            if (mode == 0) {  // ELU, write fp32 g_o AND fp16 pre-swizzled g_oh
                o0.x = o0.x > 0.f ? o0.x : (__expf(o0.x) - 1.f);
                o0.y = o0.y > 0.f ? o0.y : (__expf(o0.y) - 1.f);
                o0.z = o0.z > 0.f ? o0.z : (__expf(o0.z) - 1.f);
                o0.w = o0.w > 0.f ? o0.w : (__expf(o0.w) - 1.f);
                o1.x = o1.x > 0.f ? o1.x : (__expf(o1.x) - 1.f);
                o1.y = o1.y > 0.f ? o1.y : (__expf(o1.y) - 1.f);
                o1.z = o1.z > 0.f ? o1.z : (__expf(o1.z) - 1.f);
                o1.w = o1.w > 0.f ? o1.w : (__expf(o1.w) - 1.f);
                union { __half2 h[4]; uint4 qv; } ph;
                ph.h[0] = __floats2half2_rn(o0.x, o0.y);
                ph.h[1] = __floats2half2_rn(o0.z, o0.w);
                ph.h[2] = __floats2half2_rn(o1.x, o1.y);
                ph.h[3] = __floats2half2_rn(o1.z, o1.w);
                *(uint4*)&g_oh[((size_t)d * 8 + (q ^ (d & 7))) * 8] = ph.qv;
            }
            float4* orow = (float4*)(out + (size_t)d * CH);
            orow[q * 2]     = o0;
            orow[q * 2 + 1] = o1;
        }
    }
}

// ---------------- launch ----------------
extern "C" void kernel_launch(void* const* d_in, const int* in_sizes, int n_in,
                              void* d_out, int out_size) {
    const float* x     = (const float*)d_in[0];
    const int*   ei    = (const int*)d_in[1];
    const float* W1    = (const float*)d_in[2];
    const float* asr1  = (const float*)d_in[3];
    const float* adt1  = (const float*)d_in[4];
    const float* b1    = (const float*)d_in[5];
    const float* W2    = (const float*)d_in[6];
    const float* asr2  = (const float*)d_in[7];
    const float* adt2  = (const float*)d_in[8];
    const float* b2    = (const float*)d_in[9];
    const float* W3    = (const float*)d_in[10];
    const float* asr3  = (const float*)d_in[11];
    const float* adt3  = (const float*)d_in[12];
    const float* b3    = (const float*)d_in[13];

    int n = in_sizes[0] / 128;   // 50000
    int E = in_sizes[1] / 2;     // 800000
    float* dout = (float*)d_out;

    csr_kernel<<<CSR_BLOCKS, 256>>>(ei, x, W1, W2, W3, E, n);

    int aggGrid = (n * 32 + 255) / 256;
    int gemmGrid = (n + 127) / 128;

    gemm_alpha_kernel<128><<<gemmGrid, 256>>>(0, asr1, adt1, n);
    agg_kernel<<<aggGrid, 256>>>(b1, dout, n, 0);

    gemm_alpha_kernel<64><<<gemmGrid, 256>>>(1, asr2, adt2, n);
    agg_kernel<<<aggGrid, 256>>>(b2, dout, n, 0);

    gemm_alpha_kernel<64><<<gemmGrid, 256>>>(2, asr3, adt3, n);
    agg_kernel<<<aggGrid, 256>>>(b3, dout, n, 1);
}

// round 14
// speedup vs baseline: 3.5997x; 1.0317x over previous
#include <cuda_runtime.h>
#include <cuda_fp16.h>

#define NN 50000
#define EE 800000
#define ET (EE + NN)
#define CH 64
#define CSR_BLOCKS 592   // 148 SMs x 4 blocks co-resident

// ---------------- scratch (static device globals; no allocation) ----------------
__device__ __align__(256) __half g_h[(size_t)NN * CH];    // gemm out fp16 (row=128B)
__device__ __align__(256) __half g_oh[(size_t)NN * CH];   // agg out fp16, pre-swizzled
__device__ __align__(256) __half g_xh[(size_t)NN * 128];  // layer-1 input fp16, pre-swizzled
__device__ __align__(256) __half g_wt1[64 * 128];         // W1^T fp16 pre-swizzled
__device__ __align__(256) __half g_wt2[64 * 64];
__device__ __align__(256) __half g_wt3[64 * 64];
__device__ float g_as[NN];
__device__ float g_ad[NN];
__device__ int   g_deg[NN];
__device__ int   g_cur[NN];
__device__ int   g_off[NN + 1];
__device__ int   g_bsum[256];
__device__ int   g_ssrc[ET];
__device__ unsigned g_barcnt;
__device__ unsigned g_bargen;

// ---------------- software grid barrier ----------------
__device__ __forceinline__ void gridbar() {
    __syncthreads();
    __threadfence();
    if (threadIdx.x == 0) {
        unsigned gen = *(volatile unsigned*)&g_bargen;
        if (atomicAdd(&g_barcnt, 1u) == (unsigned)(CSR_BLOCKS - 1)) {
            g_barcnt = 0;
            __threadfence();
            atomicAdd(&g_bargen, 1u);
        } else {
            while (*(volatile unsigned*)&g_bargen == gen) { }
        }
    }
    __syncthreads();
}

// ---------------- fused CSR build + fp16 precompute ----------------
__global__ __launch_bounds__(256, 4) void csr_kernel(
        const int* __restrict__ ei, const float* __restrict__ x,
        const float* __restrict__ W1, const float* __restrict__ W2,
        const float* __restrict__ W3, int E, int n) {
    const int tid = threadIdx.x;
    const int gt = blockIdx.x * 256 + tid;
    const int gstride = CSR_BLOCKS * 256;
    const int nbt = (n + 255) / 256;
    const int E4 = E >> 2;          // E divisible by 4 (scalar tail below if not)

    // phase 0a: init degree counters to 1 (self-loop pre-counted)
    for (int i = gt; i < n; i += gstride) g_deg[i] = 1;

    // phase 0b: convert x -> g_xh (fp16, pre-swizzled u^(row&7)), CU=16
    for (int idx = gt; idx < n * 16; idx += gstride) {
        int row = idx >> 4, u = idx & 15;
        const float4* xp = (const float4*)(x + (size_t)row * 128 + u * 8);
        float4 v0 = xp[0], v1 = xp[1];
        union { __half2 h[4]; uint4 q; } pk;
        pk.h[0] = __floats2half2_rn(v0.x, v0.y);
        pk.h[1] = __floats2half2_rn(v0.z, v0.w);
        pk.h[2] = __floats2half2_rn(v1.x, v1.y);
        pk.h[3] = __floats2half2_rn(v1.z, v1.w);
        *(uint4*)&g_xh[((size_t)row * 16 + (u ^ (row & 7))) * 8] = pk.q;
    }
    // phase 0c: transpose+convert weights (pre-swizzled u^(nn&7))
    for (int idx = gt; idx < 64 * 16; idx += gstride) {   // W1: CU=16
        int nn = idx >> 4, u = idx & 15;
        union { __half2 h[4]; uint4 q; } pk;
        #pragma unroll
        for (int j = 0; j < 4; j++) {
            float w0 = W1[(size_t)(u * 8 + j * 2) * CH + nn];
            float w1 = W1[(size_t)(u * 8 + j * 2 + 1) * CH + nn];
            pk.h[j] = __floats2half2_rn(w0, w1);
        }
        *(uint4*)&g_wt1[(nn * 16 + (u ^ (nn & 7))) * 8] = pk.q;
    }
    for (int idx = gt; idx < 64 * 8 * 2; idx += gstride) {  // W2+W3: CU=8
        int which = idx >= 64 * 8;
        int id2 = idx - which * 64 * 8;
        int nn = id2 >> 3, u = id2 & 7;
        const float* W = which ? W3 : W2;
        union { __half2 h[4]; uint4 q; } pk;
        #pragma unroll
        for (int j = 0; j < 4; j++) {
            float w0 = W[(size_t)(u * 8 + j * 2) * CH + nn];
            float w1 = W[(size_t)(u * 8 + j * 2 + 1) * CH + nn];
            pk.h[j] = __floats2half2_rn(w0, w1);
        }
        __half* dst = which ? g_wt3 : g_wt2;
        *(uint4*)&dst[(nn * 8 + (u ^ (nn & 7))) * 8] = pk.q;
    }
    gridbar();

    // phase 1: count in-degree, vectorized x4 (no-return atomics -> RED)
    for (int q = gt; q < E4; q += gstride) {
        int4 d4 = *(const int4*)&ei[E + q * 4];
        atomicAdd(&g_deg[d4.x], 1);
        atomicAdd(&g_deg[d4.y], 1);
        atomicAdd(&g_deg[d4.z], 1);
        atomicAdd(&g_deg[d4.w], 1);
    }
    for (int e = E4 * 4 + gt; e < E; e += gstride)   // scalar tail (empty when E%4==0)
        atomicAdd(&g_deg[ei[E + e]], 1);
    gridbar();

    // phase 2: per-tile scan
    if ((int)blockIdx.x < nbt) {
        __shared__ int wsum[8];
        __shared__ int wpre[8];
        int i = blockIdx.x * 256 + tid;
        int lane = tid & 31, wid = tid >> 5;
        int v = (i < n) ? __ldcg(&g_deg[i]) : 0;
        int incl = v;
        #pragma unroll
        for (int off = 1; off < 32; off <<= 1) {
            int t = __shfl_up_sync(0xffffffffu, incl, off);
            if (lane >= off) incl += t;
        }
        if (lane == 31) wsum[wid] = incl;
        __syncthreads();
        if (tid == 0) {
            int run = 0;
            #pragma unroll
            for (int w = 0; w < 8; w++) { wpre[w] = run; run += wsum[w]; }
            g_bsum[blockIdx.x] = run;
        }
        __syncthreads();
        if (i < n) g_off[i] = wpre[wid] + incl - v;
    }
    gridbar();

    // phase 3: prefix-add + cursors
    if ((int)blockIdx.x < nbt) {
        __shared__ int spre;
        if (tid < 32) {
            int pre = 0, totdeg = 0;
            for (int i = tid; i < nbt; i += 32) {
                int v = __ldcg(&g_bsum[i]);
                totdeg += v;
                if (i < (int)blockIdx.x) pre += v;
            }
            #pragma unroll
            for (int o = 16; o; o >>= 1) {
                pre    += __shfl_xor_sync(0xffffffffu, pre, o);
                totdeg += __shfl_xor_sync(0xffffffffu, totdeg, o);
            }
            if (tid == 0) {
                spre = pre;
                if (blockIdx.x == 0) g_off[n] = totdeg;
            }
        }
        __syncthreads();
        int i = blockIdx.x * 256 + tid;
        if (i < n) {
            int v = g_off[i] + spre;
            g_off[i] = v;
            g_cur[i] = v;
        }
    }
    gridbar();

    // phase 4: fill CSR, vectorized x4 (4 independent atomic-return chains in flight)
    for (int q = gt; q < E4; q += gstride) {
        int4 s4 = *(const int4*)&ei[q * 4];
        int4 d4 = *(const int4*)&ei[E + q * 4];
        int p0 = atomicAdd(&g_cur[d4.x], 1);
        int p1 = atomicAdd(&g_cur[d4.y], 1);
        int p2 = atomicAdd(&g_cur[d4.z], 1);
        int p3 = atomicAdd(&g_cur[d4.w], 1);
        g_ssrc[p0] = s4.x;
        g_ssrc[p1] = s4.y;
        g_ssrc[p2] = s4.z;
        g_ssrc[p3] = s4.w;
    }
    for (int e = E4 * 4 + gt; e < E; e += gstride) {  // scalar tail
        int p = atomicAdd(&g_cur[ei[E + e]], 1);
        g_ssrc[p] = ei[e];
    }
    for (int i = gt; i < n; i += gstride) {           // self-loops
        int p = atomicAdd(&g_cur[i], 1);
        g_ssrc[p] = i;
    }
}

// ---------------- tensor-core GEMM (HMMA m16n8k16) + fused alpha ----------------
template <int CIN>
__global__ __launch_bounds__(256, 3) void gemm_alpha_kernel(
        int sel, const float* __restrict__ avs, const float* __restrict__ avd, int n) {
    constexpr int CU = CIN / 8;
    __shared__ __half Xs[128 * CIN];
    __shared__ __half Ws[64 * CIN];

    const __half* Xh = (sel == 0) ? g_xh : g_oh;
    const __half* Wt = (sel == 0) ? g_wt1 : ((sel == 1) ? g_wt2 : g_wt3);

    int tid = threadIdx.x;
    int lane = tid & 31;
    int wid = tid >> 5;
    int m0 = blockIdx.x * 128;

    if (m0 + 128 <= n) {
        const uint4* src = (const uint4*)(Xh + (size_t)m0 * CIN);
        uint4* dst = (uint4*)Xs;
        #pragma unroll
        for (int i = 0; i < 128 * CU / 256; i++)
            dst[tid + i * 256] = src[tid + i * 256];
    } else {
        for (int idx = tid; idx < 128 * CU; idx += 256) {
            int row = idx / CU, u = idx - row * CU;
            int rowc = min(m0 + row, n - 1);
            *(uint4*)&Xs[(size_t)idx * 8] = *(const uint4*)&Xh[((size_t)rowc * CU + u) * 8];
        }
    }
    {
        const uint4* src = (const uint4*)Wt;
        uint4* dst = (uint4*)Ws;
        #pragma unroll
        for (int i = 0; i < 64 * CU / 256; i++)
            dst[tid + i * 256] = src[tid + i * 256];
    }
    __syncthreads();

    unsigned xsb;
    {
        unsigned long long t;
        asm("cvta.to.shared.u64 %0, %1;" : "=l"(t) : "l"(Xs)); xsb = (unsigned)t;
    }

    float c[8][4];
    #pragma unroll
    for (int t = 0; t < 8; t++) { c[t][0] = c[t][1] = c[t][2] = c[t][3] = 0.f; }

    int arow = lane & 15;
    int aub = lane >> 4;
    int bg = lane >> 2;
    int bw = lane & 3;

    #pragma unroll
    for (int ks = 0; ks < CIN / 16; ks++) {
        unsigned a0, a1, a2, a3;
        int au = (ks * 2 + aub) ^ (arow & 7);
        unsigned aaddr = xsb + ((wid * 16 + arow) * CU + au) * 16;
        asm volatile("ldmatrix.sync.aligned.m8n8.x4.shared.b16 {%0,%1,%2,%3}, [%4];"
                     : "=r"(a0), "=r"(a1), "=r"(a2), "=r"(a3) : "r"(aaddr));
        #pragma unroll
        for (int t = 0; t < 8; t++) {
            int nrow = t * 8 + bg;
            unsigned b0 = *(const unsigned*)((const char*)Ws +
                          ((nrow * CU + ((ks * 2) ^ bg)) * 16 + bw * 4));
            unsigned b1 = *(const unsigned*)((const char*)Ws +
                          ((nrow * CU + ((ks * 2 + 1) ^ bg)) * 16 + bw * 4));
            asm volatile("mma.sync.aligned.m16n8k16.row.col.f32.f16.f16.f32 "
                         "{%0,%1,%2,%3}, {%4,%5,%6,%7}, {%8,%9}, {%0,%1,%2,%3};"
                         : "+f"(c[t][0]), "+f"(c[t][1]), "+f"(c[t][2]), "+f"(c[t][3])
                         : "r"(a0), "r"(a1), "r"(a2), "r"(a3), "r"(b0), "r"(b1));
        }
    }

    int r0 = m0 + wid * 16 + (lane >> 2);
    int r1 = r0 + 8;
    float psA = 0.f, pdA = 0.f, psB = 0.f, pdB = 0.f;
    #pragma unroll
    for (int t = 0; t < 8; t++) {
        int col = t * 8 + (lane & 3) * 2;
        float as0 = avs[col], as1 = avs[col + 1];
        float ad0 = avd[col], ad1 = avd[col + 1];
        psA += c[t][0] * as0 + c[t][1] * as1;
        pdA += c[t][0] * ad0 + c[t][1] * ad1;
        psB += c[t][2] * as0 + c[t][3] * as1;
        pdB += c[t][2] * ad0 + c[t][3] * ad1;
        if (r0 < n)
            *(__half2*)((char*)g_h + ((size_t)r0 << 7) + col * 2) = __floats2half2_rn(c[t][0], c[t][1]);
        if (r1 < n)
            *(__half2*)((char*)g_h + ((size_t)r1 << 7) + col * 2) = __floats2half2_rn(c[t][2], c[t][3]);
    }
    #pragma unroll
    for (int o = 1; o <= 2; o <<= 1) {
        psA += __shfl_xor_sync(0xffffffffu, psA, o);
        pdA += __shfl_xor_sync(0xffffffffu, pdA, o);
        psB += __shfl_xor_sync(0xffffffffu, psB, o);
        pdB += __shfl_xor_sync(0xffffffffu, pdB, o);
    }
    if ((lane & 3) == 0) {
        if (r0 < n) { g_as[r0] = psA; g_ad[r0] = pdA; }
        if (r1 < n) { g_as[r1] = psB; g_ad[r1] = pdB; }
    }
}

// ---------------- segment softmax + weighted aggregation (fp16 gather) ----------------
// mode 0: write fp16 pre-swizzled g_oh only. mode 1: write fp32 dout.
__global__ void agg_kernel(const float* __restrict__ bias,
                           float* __restrict__ dout, int n, int mode) {
    int lane = threadIdx.x & 31;
    int qid = lane >> 3;
    int q = lane & 7;
    int gw = (blockIdx.x * blockDim.x + threadIdx.x) >> 5;
    int nw = (gridDim.x * blockDim.x) >> 5;

    for (int d = gw; d < n; d += nw) {
        int beg = g_off[d], end = g_off[d + 1];
        float adv = g_ad[d];

        float acc[8];
        #pragma unroll
        for (int i = 0; i < 8; i++) acc[i] = 0.f;
        float denp = 0.f;

        for (int base = beg; base < end; base += 32) {
            int j = base + lane;
            int s = 0;
            float w = 0.f;
            if (j < end) {
                s = g_ssrc[j];
                float e = g_as[s] + adv;
                e = e > 0.f ? e : 0.2f * e;
                w = __expf(e);
            }
            denp += w;
            int cnt = min(32, end - base);
            #pragma unroll 4
            for (int k = 0; k < cnt; k += 4) {
                int e = k + qid;
                int   sk = __shfl_sync(0xffffffffu, s, e & 31);
                float wk = __shfl_sync(0xffffffffu, w, e & 31);
                if (e >= cnt) wk = 0.f;
                uint4 u = *(const uint4*)((const char*)g_h + ((size_t)sk << 7) + (q << 4));
                float2 f0 = __half22float2(*(__half2*)&u.x);
                float2 f1 = __half22float2(*(__half2*)&u.y);
                float2 f2 = __half22float2(*(__half2*)&u.z);
                float2 f3 = __half22float2(*(__half2*)&u.w);
                acc[0] = fmaf(wk, f0.x, acc[0]);
                acc[1] = fmaf(wk, f0.y, acc[1]);
                acc[2] = fmaf(wk, f1.x, acc[2]);
                acc[3] = fmaf(wk, f1.y, acc[3]);
                acc[4] = fmaf(wk, f2.x, acc[4]);
                acc[5] = fmaf(wk, f2.y, acc[5]);
                acc[6] = fmaf(wk, f3.x, acc[6]);
                acc[7] = fmaf(wk, f3.y, acc[7]);
            }
        }
        #pragma unroll
        for (int i = 0; i < 8; i++) {
            acc[i] += __shfl_xor_sync(0xffffffffu, acc[i], 8);
            acc[i] += __shfl_xor_sync(0xffffffffu, acc[i], 16);
        }
        float den = denp;
        #pragma unroll
        for (int o = 16; o; o >>= 1) den += __shfl_xor_sync(0xffffffffu, den, o);

        if (qid == 0) {
            float inv = 1.f / den;
            const float4* b4 = (const float4*)bias;
            float4 bv0 = b4[q * 2], bv1 = b4[q * 2 + 1];
            float4 o0, o1;
            o0.x = acc[0] * inv + bv0.x;
            o0.y = acc[1] * inv + bv0.y;
            o0.z = acc[2] * inv + bv0.z;
            o0.w = acc[3] * inv + bv0.w;
            o1.x = acc[4] * inv + bv1.x;
            o1.y = acc[5] * inv + bv1.y;
            o1.z = acc[6] * inv + bv1.z;
            o1.w = acc[7] * inv + bv1.w;
            if (mode == 0) {  // ELU -> fp16 pre-swizzled g_oh only
                o0.x = o0.x > 0.f ? o0.x : (__expf(o0.x) - 1.f);
                o0.y = o0.y > 0.f ? o0.y : (__expf(o0.y) - 1.f);
                o0.z = o0.z > 0.f ? o0.z : (__expf(o0.z) - 1.f);
                o0.w = o0.w > 0.f ? o0.w : (__expf(o0.w) - 1.f);
                o1.x = o1.x > 0.f ? o1.x : (__expf(o1.x) - 1.f);
                o1.y = o1.y > 0.f ? o1.y : (__expf(o1.y) - 1.f);
                o1.z = o1.z > 0.f ? o1.z : (__expf(o1.z) - 1.f);
                o1.w = o1.w > 0.f ? o1.w : (__expf(o1.w) - 1.f);
                union { __half2 h[4]; uint4 qv; } ph;
                ph.h[0] = __floats2half2_rn(o0.x, o0.y);
                ph.h[1] = __floats2half2_rn(o0.z, o0.w);
                ph.h[2] = __floats2half2_rn(o1.x, o1.y);
                ph.h[3] = __floats2half2_rn(o1.z, o1.w);
                *(uint4*)&g_oh[((size_t)d * 8 + (q ^ (d & 7))) * 8] = ph.qv;
            } else {
                float4* orow = (float4*)(dout + (size_t)d * CH);
                orow[q * 2]     = o0;
                orow[q * 2 + 1] = o1;
            }
        }
    }
}

// ---------------- launch ----------------
extern "C" void kernel_launch(void* const* d_in, const int* in_sizes, int n_in,
                              void* d_out, int out_size) {
    const float* x     = (const float*)d_in[0];
    const int*   ei    = (const int*)d_in[1];
    const float* W1    = (const float*)d_in[2];
    const float* asr1  = (const float*)d_in[3];
    const float* adt1  = (const float*)d_in[4];
    const float* b1    = (const float*)d_in[5];
    const float* W2    = (const float*)d_in[6];
    const float* asr2  = (const float*)d_in[7];
    const float* adt2  = (const float*)d_in[8];
    const float* b2    = (const float*)d_in[9];
    const float* W3    = (const float*)d_in[10];
    const float* asr3  = (const float*)d_in[11];
    const float* adt3  = (const float*)d_in[12];
    const float* b3    = (const float*)d_in[13];

    int n = in_sizes[0] / 128;   // 50000
    int E = in_sizes[1] / 2;     // 800000
    float* dout = (float*)d_out;

    csr_kernel<<<CSR_BLOCKS, 256>>>(ei, x, W1, W2, W3, E, n);

    int aggGrid = (n * 32 + 255) / 256;
    int gemmGrid = (n + 127) / 128;

    gemm_alpha_kernel<128><<<gemmGrid, 256>>>(0, asr1, adt1, n);
    agg_kernel<<<aggGrid, 256>>>(b1, dout, n, 0);

    gemm_alpha_kernel<64><<<gemmGrid, 256>>>(1, asr2, adt2, n);
    agg_kernel<<<aggGrid, 256>>>(b2, dout, n, 0);

    gemm_alpha_kernel<64><<<gemmGrid, 256>>>(2, asr3, adt3, n);
    agg_kernel<<<aggGrid, 256>>>(b3, dout, n, 1);
}

// round 15
// speedup vs baseline: 3.8235x; 1.0622x over previous
#include <cuda_runtime.h>
#include <cuda_fp16.h>

#define NN 50000
#define EE 800000
#define ET (EE + NN)
#define CH 64

// ---------------- scratch (static device globals; no allocation) ----------------
__device__ __align__(256) __half g_h[(size_t)NN * CH];    // gemm out fp16 (row=128B)
__device__ __align__(256) __half g_oh[(size_t)NN * CH];   // agg out fp16, pre-swizzled
__device__ __align__(256) __half g_xh[(size_t)NN * 128];  // layer-1 input fp16, pre-swizzled
__device__ __align__(256) __half g_wt1[64 * 128];         // W1^T fp16 pre-swizzled
__device__ __align__(256) __half g_wt2[64 * 64];
__device__ __align__(256) __half g_wt3[64 * 64];
__device__ float g_as[NN];
__device__ float g_ad[NN];
__device__ int   g_deg[NN];
__device__ int   g_cur[NN];
__device__ int   g_off[NN + 1];
__device__ int   g_bsum[256];
__device__ int   g_ssrc[ET];

// ---------------- static stream/event resources (host-side; created at load) ----------------
static cudaStream_t g_s2;
static cudaEvent_t g_ef, g_ej;
static bool g_fork_ok = false;
namespace {
struct StreamInit {
    StreamInit() {
        g_fork_ok =
            cudaStreamCreateWithFlags(&g_s2, cudaStreamNonBlocking) == cudaSuccess &&
            cudaEventCreateWithFlags(&g_ef, cudaEventDisableTiming) == cudaSuccess &&
            cudaEventCreateWithFlags(&g_ej, cudaEventDisableTiming) == cudaSuccess;
    }
};
StreamInit g_si;
}

// ---------------- fp16 precompute: x and weights ----------------
__global__ void conv_kernel(const float* __restrict__ x,
                            const float* __restrict__ W1,
                            const float* __restrict__ W2,
                            const float* __restrict__ W3, int n) {
    int gt = blockIdx.x * blockDim.x + threadIdx.x;
    int gstride = gridDim.x * blockDim.x;

    // x -> g_xh (fp16, pre-swizzled u^(row&7)), CU=16
    for (int idx = gt; idx < n * 16; idx += gstride) {
        int row = idx >> 4, u = idx & 15;
        const float4* xp = (const float4*)(x + (size_t)row * 128 + u * 8);
        float4 v0 = xp[0], v1 = xp[1];
        union { __half2 h[4]; uint4 q; } pk;
        pk.h[0] = __floats2half2_rn(v0.x, v0.y);
        pk.h[1] = __floats2half2_rn(v0.z, v0.w);
        pk.h[2] = __floats2half2_rn(v1.x, v1.y);
        pk.h[3] = __floats2half2_rn(v1.z, v1.w);
        *(uint4*)&g_xh[((size_t)row * 16 + (u ^ (row & 7))) * 8] = pk.q;
    }
    // W1^T (CU=16)
    for (int idx = gt; idx < 64 * 16; idx += gstride) {
        int nn = idx >> 4, u = idx & 15;
        union { __half2 h[4]; uint4 q; } pk;
        #pragma unroll
        for (int j = 0; j < 4; j++) {
            float w0 = W1[(size_t)(u * 8 + j * 2) * CH + nn];
            float w1 = W1[(size_t)(u * 8 + j * 2 + 1) * CH + nn];
            pk.h[j] = __floats2half2_rn(w0, w1);
        }
        *(uint4*)&g_wt1[(nn * 16 + (u ^ (nn & 7))) * 8] = pk.q;
    }
    // W2^T + W3^T (CU=8)
    for (int idx = gt; idx < 64 * 8 * 2; idx += gstride) {
        int which = idx >= 64 * 8;
        int id2 = idx - which * 64 * 8;
        int nn = id2 >> 3, u = id2 & 7;
        const float* W = which ? W3 : W2;
        union { __half2 h[4]; uint4 q; } pk;
        #pragma unroll
        for (int j = 0; j < 4; j++) {
            float w0 = W[(size_t)(u * 8 + j * 2) * CH + nn];
            float w1 = W[(size_t)(u * 8 + j * 2 + 1) * CH + nn];
            pk.h[j] = __floats2half2_rn(w0, w1);
        }
        __half* dst = which ? g_wt3 : g_wt2;
        *(uint4*)&dst[(nn * 8 + (u ^ (nn & 7))) * 8] = pk.q;
    }
}

// ---------------- CSR build chain (separate kernels; kernel boundary = sync) ----------------
__global__ void zero_kernel(int n) {
    int stride = gridDim.x * blockDim.x;
    for (int i = blockIdx.x * blockDim.x + threadIdx.x; i < n; i += stride)
        g_deg[i] = 1;   // self-loop pre-counted
}

__global__ void count_kernel(const int* __restrict__ ei, int E, int n) {
    int gt = blockIdx.x * blockDim.x + threadIdx.x;
    int gstride = gridDim.x * blockDim.x;
    int E4 = E >> 2;
    for (int q = gt; q < E4; q += gstride) {
        int4 d4 = *(const int4*)&ei[E + q * 4];
        atomicAdd(&g_deg[d4.x], 1);
        atomicAdd(&g_deg[d4.y], 1);
        atomicAdd(&g_deg[d4.z], 1);
        atomicAdd(&g_deg[d4.w], 1);
    }
    for (int e = E4 * 4 + gt; e < E; e += gstride)
        atomicAdd(&g_deg[ei[E + e]], 1);
}

// per-block exclusive scan of g_deg -> g_off, block sums -> g_bsum
__global__ void scan1_kernel(int n) {
    __shared__ int wsum[8];
    __shared__ int wpre[8];
    int i = blockIdx.x * blockDim.x + threadIdx.x;
    int lane = threadIdx.x & 31, wid = threadIdx.x >> 5;
    int v = (i < n) ? g_deg[i] : 0;
    int incl = v;
    #pragma unroll
    for (int off = 1; off < 32; off <<= 1) {
        int t = __shfl_up_sync(0xffffffffu, incl, off);
        if (lane >= off) incl += t;
    }
    if (lane == 31) wsum[wid] = incl;
    __syncthreads();
    if (threadIdx.x == 0) {
        int run = 0;
        #pragma unroll
        for (int w = 0; w < 8; w++) { wpre[w] = run; run += wsum[w]; }
        g_bsum[blockIdx.x] = run;
    }
    __syncthreads();
    if (i < n) g_off[i] = wpre[wid] + incl - v;
}

// each block recomputes its block-sum prefix, adds it, inits cursors
__global__ void scan23_kernel(int nb, int n) {
    __shared__ int spre;
    if (threadIdx.x < 32) {
        int lane = threadIdx.x;
        int pre = 0, tot = 0;
        for (int i = lane; i < nb; i += 32) {
            int v = g_bsum[i];
            tot += v;
            if (i < (int)blockIdx.x) pre += v;
        }
        #pragma unroll
        for (int o = 16; o; o >>= 1) {
            pre += __shfl_xor_sync(0xffffffffu, pre, o);
            tot += __shfl_xor_sync(0xffffffffu, tot, o);
        }
        if (lane == 0) {
            spre = pre;
            if (blockIdx.x == 0) g_off[n] = tot;
        }
    }
    __syncthreads();
    int i = blockIdx.x * blockDim.x + threadIdx.x;
    if (i < n) {
        int v = g_off[i] + spre;
        g_off[i] = v;
        g_cur[i] = v;
    }
}

__global__ void fill_kernel(const int* __restrict__ ei, int E, int n) {
    int gt = blockIdx.x * blockDim.x + threadIdx.x;
    int gstride = gridDim.x * blockDim.x;
    int E4 = E >> 2;
    for (int q = gt; q < E4; q += gstride) {
        int4 s4 = *(const int4*)&ei[q * 4];
        int4 d4 = *(const int4*)&ei[E + q * 4];
        int p0 = atomicAdd(&g_cur[d4.x], 1);
        int p1 = atomicAdd(&g_cur[d4.y], 1);
        int p2 = atomicAdd(&g_cur[d4.z], 1);
        int p3 = atomicAdd(&g_cur[d4.w], 1);
        g_ssrc[p0] = s4.x;
        g_ssrc[p1] = s4.y;
        g_ssrc[p2] = s4.z;
        g_ssrc[p3] = s4.w;
    }
    for (int e = E4 * 4 + gt; e < E; e += gstride) {
        int p = atomicAdd(&g_cur[ei[E + e]], 1);
        g_ssrc[p] = ei[e];
    }
    for (int i = gt; i < n; i += gstride) {           // self-loops
        int p = atomicAdd(&g_cur[i], 1);
        g_ssrc[p] = i;
    }
}

// ---------------- tensor-core GEMM (HMMA m16n8k16) + fused alpha ----------------
template <int CIN>
__global__ __launch_bounds__(256, 3) void gemm_alpha_kernel(
        int sel, const float* __restrict__ avs, const float* __restrict__ avd, int n) {
    constexpr int CU = CIN / 8;
    __shared__ __half Xs[128 * CIN];
    __shared__ __half Ws[64 * CIN];

    const __half* Xh = (sel == 0) ? g_xh : g_oh;
    const __half* Wt = (sel == 0) ? g_wt1 : ((sel == 1) ? g_wt2 : g_wt3);

    int tid = threadIdx.x;
    int lane = tid & 31;
    int wid = tid >> 5;
    int m0 = blockIdx.x * 128;

    if (m0 + 128 <= n) {
        const uint4* src = (const uint4*)(Xh + (size_t)m0 * CIN);
        uint4* dst = (uint4*)Xs;
        #pragma unroll
        for (int i = 0; i < 128 * CU / 256; i++)
            dst[tid + i * 256] = src[tid + i * 256];
    } else {
        for (int idx = tid; idx < 128 * CU; idx += 256) {
            int row = idx / CU, u = idx - row * CU;
            int rowc = min(m0 + row, n - 1);
            *(uint4*)&Xs[(size_t)idx * 8] = *(const uint4*)&Xh[((size_t)rowc * CU + u) * 8];
        }
    }
    {
        const uint4* src = (const uint4*)Wt;
        uint4* dst = (uint4*)Ws;
        #pragma unroll
        for (int i = 0; i < 64 * CU / 256; i++)
            dst[tid + i * 256] = src[tid + i * 256];
    }
    __syncthreads();

    unsigned xsb;
    {
        unsigned long long t;
        asm("cvta.to.shared.u64 %0, %1;" : "=l"(t) : "l"(Xs)); xsb = (unsigned)t;
    }

    float c[8][4];
    #pragma unroll
    for (int t = 0; t < 8; t++) { c[t][0] = c[t][1] = c[t][2] = c[t][3] = 0.f; }

    int arow = lane & 15;
    int aub = lane >> 4;
    int bg = lane >> 2;
    int bw = lane & 3;

    #pragma unroll
    for (int ks = 0; ks < CIN / 16; ks++) {
        unsigned a0, a1, a2, a3;
        int au = (ks * 2 + aub) ^ (arow & 7);
        unsigned aaddr = xsb + ((wid * 16 + arow) * CU + au) * 16;
        asm volatile("ldmatrix.sync.aligned.m8n8.x4.shared.b16 {%0,%1,%2,%3}, [%4];"
                     : "=r"(a0), "=r"(a1), "=r"(a2), "=r"(a3) : "r"(aaddr));
        #pragma unroll
        for (int t = 0; t < 8; t++) {
            int nrow = t * 8 + bg;
            unsigned b0 = *(const unsigned*)((const char*)Ws +
                          ((nrow * CU + ((ks * 2) ^ bg)) * 16 + bw * 4));
            unsigned b1 = *(const unsigned*)((const char*)Ws +
                          ((nrow * CU + ((ks * 2 + 1) ^ bg)) * 16 + bw * 4));
            asm volatile("mma.sync.aligned.m16n8k16.row.col.f32.f16.f16.f32 "
                         "{%0,%1,%2,%3}, {%4,%5,%6,%7}, {%8,%9}, {%0,%1,%2,%3};"
                         : "+f"(c[t][0]), "+f"(c[t][1]), "+f"(c[t][2]), "+f"(c[t][3])
                         : "r"(a0), "r"(a1), "r"(a2), "r"(a3), "r"(b0), "r"(b1));
        }
    }

    int r0 = m0 + wid * 16 + (lane >> 2);
    int r1 = r0 + 8;
    float psA = 0.f, pdA = 0.f, psB = 0.f, pdB = 0.f;
    #pragma unroll
    for (int t = 0; t < 8; t++) {
        int col = t * 8 + (lane & 3) * 2;
        float as0 = avs[col], as1 = avs[col + 1];
        float ad0 = avd[col], ad1 = avd[col + 1];
        psA += c[t][0] * as0 + c[t][1] * as1;
        pdA += c[t][0] * ad0 + c[t][1] * ad1;
        psB += c[t][2] * as0 + c[t][3] * as1;
        pdB += c[t][2] * ad0 + c[t][3] * ad1;
        if (r0 < n)
            *(__half2*)((char*)g_h + ((size_t)r0 << 7) + col * 2) = __floats2half2_rn(c[t][0], c[t][1]);
        if (r1 < n)
            *(__half2*)((char*)g_h + ((size_t)r1 << 7) + col * 2) = __floats2half2_rn(c[t][2], c[t][3]);
    }
    #pragma unroll
    for (int o = 1; o <= 2; o <<= 1) {
        psA += __shfl_xor_sync(0xffffffffu, psA, o);
        pdA += __shfl_xor_sync(0xffffffffu, pdA, o);
        psB += __shfl_xor_sync(0xffffffffu, psB, o);
        pdB += __shfl_xor_sync(0xffffffffu, pdB, o);
    }
    if ((lane & 3) == 0) {
        if (r0 < n) { g_as[r0] = psA; g_ad[r0] = pdA; }
        if (r1 < n) { g_as[r1] = psB; g_ad[r1] = pdB; }
    }
}

// ---------------- segment softmax + weighted aggregation (fp16 gather) ----------------
__global__ void agg_kernel(const float* __restrict__ bias,
                           float* __restrict__ dout, int n, int mode) {
    int lane = threadIdx.x & 31;
    int qid = lane >> 3;
    int q = lane & 7;
    int gw = (blockIdx.x * blockDim.x + threadIdx.x) >> 5;
    int nw = (gridDim.x * blockDim.x) >> 5;

    for (int d = gw; d < n; d += nw) {
        int beg = g_off[d], end = g_off[d + 1];
        float adv = g_ad[d];

        float acc[8];
        #pragma unroll
        for (int i = 0; i < 8; i++) acc[i] = 0.f;
        float denp = 0.f;

        for (int base = beg; base < end; base += 32) {
            int j = base + lane;
            int s = 0;
            float w = 0.f;
            if (j < end) {
                s = g_ssrc[j];
                float e = g_as[s] + adv;
                e = e > 0.f ? e : 0.2f * e;
                w = __expf(e);
            }
            denp += w;
            int cnt = min(32, end - base);
            #pragma unroll 4
            for (int k = 0; k < cnt; k += 4) {
                int e = k + qid;
                int   sk = __shfl_sync(0xffffffffu, s, e & 31);
                float wk = __shfl_sync(0xffffffffu, w, e & 31);
                if (e >= cnt) wk = 0.f;
                uint4 u = *(const uint4*)((const char*)g_h + ((size_t)sk << 7) + (q << 4));
                float2 f0 = __half22float2(*(__half2*)&u.x);
                float2 f1 = __half22float2(*(__half2*)&u.y);
                float2 f2 = __half22float2(*(__half2*)&u.z);
                float2 f3 = __half22float2(*(__half2*)&u.w);
                acc[0] = fmaf(wk, f0.x, acc[0]);
                acc[1] = fmaf(wk, f0.y, acc[1]);
                acc[2] = fmaf(wk, f1.x, acc[2]);
                acc[3] = fmaf(wk, f1.y, acc[3]);
                acc[4] = fmaf(wk, f2.x, acc[4]);
                acc[5] = fmaf(wk, f2.y, acc[5]);
                acc[6] = fmaf(wk, f3.x, acc[6]);
                acc[7] = fmaf(wk, f3.y, acc[7]);
            }
        }
        #pragma unroll
        for (int i = 0; i < 8; i++) {
            acc[i] += __shfl_xor_sync(0xffffffffu, acc[i], 8);
            acc[i] += __shfl_xor_sync(0xffffffffu, acc[i], 16);
        }
        float den = denp;
        #pragma unroll
        for (int o = 16; o; o >>= 1) den += __shfl_xor_sync(0xffffffffu, den, o);

        if (qid == 0) {
            float inv = 1.f / den;
            const float4* b4 = (const float4*)bias;
            float4 bv0 = b4[q * 2], bv1 = b4[q * 2 + 1];
            float4 o0, o1;
            o0.x = acc[0] * inv + bv0.x;
            o0.y = acc[1] * inv + bv0.y;
            o0.z = acc[2] * inv + bv0.z;
            o0.w = acc[3] * inv + bv0.w;
            o1.x = acc[4] * inv + bv1.x;
            o1.y = acc[5] * inv + bv1.y;
            o1.z = acc[6] * inv + bv1.z;
            o1.w = acc[7] * inv + bv1.w;
            if (mode == 0) {  // ELU -> fp16 pre-swizzled g_oh
                o0.x = o0.x > 0.f ? o0.x : (__expf(o0.x) - 1.f);
                o0.y = o0.y > 0.f ? o0.y : (__expf(o0.y) - 1.f);
                o0.z = o0.z > 0.f ? o0.z : (__expf(o0.z) - 1.f);
                o0.w = o0.w > 0.f ? o0.w : (__expf(o0.w) - 1.f);
                o1.x = o1.x > 0.f ? o1.x : (__expf(o1.x) - 1.f);
                o1.y = o1.y > 0.f ? o1.y : (__expf(o1.y) - 1.f);
                o1.z = o1.z > 0.f ? o1.z : (__expf(o1.z) - 1.f);
                o1.w = o1.w > 0.f ? o1.w : (__expf(o1.w) - 1.f);
                union { __half2 h[4]; uint4 qv; } ph;
                ph.h[0] = __floats2half2_rn(o0.x, o0.y);
                ph.h[1] = __floats2half2_rn(o0.z, o0.w);
                ph.h[2] = __floats2half2_rn(o1.x, o1.y);
                ph.h[3] = __floats2half2_rn(o1.z, o1.w);
                *(uint4*)&g_oh[((size_t)d * 8 + (q ^ (d & 7))) * 8] = ph.qv;
            } else {
                float4* orow = (float4*)(dout + (size_t)d * CH);
                orow[q * 2]     = o0;
                orow[q * 2 + 1] = o1;
            }
        }
    }
}

// ---------------- launch ----------------
extern "C" void kernel_launch(void* const* d_in, const int* in_sizes, int n_in,
                              void* d_out, int out_size) {
    const float* x     = (const float*)d_in[0];
    const int*   ei    = (const int*)d_in[1];
    const float* W1    = (const float*)d_in[2];
    const float* asr1  = (const float*)d_in[3];
    const float* adt1  = (const float*)d_in[4];
    const float* b1    = (const float*)d_in[5];
    const float* W2    = (const float*)d_in[6];
    const float* asr2  = (const float*)d_in[7];
    const float* adt2  = (const float*)d_in[8];
    const float* b2    = (const float*)d_in[9];
    const float* W3    = (const float*)d_in[10];
    const float* asr3  = (const float*)d_in[11];
    const float* adt3  = (const float*)d_in[12];
    const float* b3    = (const float*)d_in[13];

    int n = in_sizes[0] / 128;   // 50000
    int E = in_sizes[1] / 2;     // 800000
    float* dout = (float*)d_out;

    int nb = (n + 255) / 256;
    int aggGrid = (n * 32 + 255) / 256;
    int gemmGrid = (n + 127) / 128;

    bool two = g_fork_ok;
    cudaStream_t s2 = two ? g_s2 : (cudaStream_t)0;

    if (two) {
        cudaEventRecord(g_ef, 0);            // fork from legacy stream
        cudaStreamWaitEvent(s2, g_ef, 0);
    }
    // CSR chain (stream s2; sequential fallback on legacy if !two)
    zero_kernel<<<96, 256, 0, s2>>>(n);
    count_kernel<<<832, 256, 0, s2>>>(ei, E, n);
    scan1_kernel<<<nb, 256, 0, s2>>>(n);
    scan23_kernel<<<nb, 256, 0, s2>>>(nb, n);
    fill_kernel<<<832, 256, 0, s2>>>(ei, E, n);
    if (two) cudaEventRecord(g_ej, s2);

    // main stream: conversion + layer-1 GEMM (independent of CSR)
    conv_kernel<<<416, 256>>>(x, W1, W2, W3, n);
    gemm_alpha_kernel<128><<<gemmGrid, 256>>>(0, asr1, adt1, n);

    if (two) cudaStreamWaitEvent(0, g_ej, 0);  // join: agg1 needs CSR

    agg_kernel<<<aggGrid, 256>>>(b1, dout, n, 0);
    gemm_alpha_kernel<64><<<gemmGrid, 256>>>(1, asr2, adt2, n);
    agg_kernel<<<aggGrid, 256>>>(b2, dout, n, 0);
    gemm_alpha_kernel<64><<<gemmGrid, 256>>>(2, asr3, adt3, n);
    agg_kernel<<<aggGrid, 256>>>(b3, dout, n, 1);
}